// round 1
// baseline (speedup 1.0000x reference)
#include <cuda_runtime.h>
#include <cuda_bf16.h>
#include <math.h>

// Problem constants
#define NVOX 147456
#define CDIM 192
#define NH 8
#define DH 24
#define DFF 768
#define SETSZ 36
#define NSET 4096

// ---------------------------------------------------------------------------
// Scratch buffers (device globals; allocation-free per harness rules)
// ---------------------------------------------------------------------------
__device__ float g_bufA[(size_t)NVOX * CDIM];
__device__ float g_bufB[(size_t)NVOX * CDIM];
__device__ float g_bufC[(size_t)NVOX * CDIM];
__device__ float g_bufD[(size_t)NVOX * CDIM];
__device__ float g_bufE[(size_t)NVOX * CDIM];
__device__ float g_bufH[(size_t)NVOX * DFF];

// ---------------------------------------------------------------------------
// Gather: for flattened set position p, voxel v = inds[p]:
//   g[p]   = out[v] + pos[v]   (q/k input)
//   sfb[p] = out[v]            (v input)
// inds base selected by shift = block_id % 2 and layer index.
// ---------------------------------------------------------------------------
__global__ void gather_kernel(const float* __restrict__ out,
                              const float* __restrict__ pos,
                              const int* __restrict__ inds_all,
                              const int* __restrict__ block_id,
                              int layer,
                              float* __restrict__ g,
                              float* __restrict__ sfb) {
    int gid = blockIdx.x * blockDim.x + threadIdx.x;
    const int TOT = NVOX * (CDIM / 4);
    if (gid >= TOT) return;
    int p = gid / (CDIM / 4);
    int c4 = gid % (CDIM / 4);
    int shift = block_id[0] & 1;
    const int* inds = inds_all + ((size_t)shift * 2 + layer) * NVOX;
    int v = inds[p];
    float4 f = reinterpret_cast<const float4*>(out)[(size_t)v * (CDIM / 4) + c4];
    float4 pp = reinterpret_cast<const float4*>(pos)[(size_t)v * (CDIM / 4) + c4];
    reinterpret_cast<float4*>(sfb)[gid] = f;
    float4 r;
    r.x = f.x + pp.x; r.y = f.y + pp.y; r.z = f.z + pp.z; r.w = f.w + pp.w;
    reinterpret_cast<float4*>(g)[gid] = r;
}

// ---------------------------------------------------------------------------
// Scatter + residual: resid[v] = out[v] + oproj[p]  where v = inds[p].
// inds is a permutation of [0,N) so this is conflict-free.
// ---------------------------------------------------------------------------
__global__ void scatter_kernel(const float* __restrict__ out,
                               const float* __restrict__ oproj,
                               const int* __restrict__ inds_all,
                               const int* __restrict__ block_id,
                               int layer,
                               float* __restrict__ resid) {
    int gid = blockIdx.x * blockDim.x + threadIdx.x;
    const int TOT = NVOX * (CDIM / 4);
    if (gid >= TOT) return;
    int p = gid / (CDIM / 4);
    int c4 = gid % (CDIM / 4);
    int shift = block_id[0] & 1;
    const int* inds = inds_all + ((size_t)shift * 2 + layer) * NVOX;
    int v = inds[p];
    float4 a = reinterpret_cast<const float4*>(out)[(size_t)v * (CDIM / 4) + c4];
    float4 b = reinterpret_cast<const float4*>(oproj)[gid];
    float4 r;
    r.x = a.x + b.x; r.y = a.y + b.y; r.z = a.z + b.z; r.w = a.w + b.w;
    reinterpret_cast<float4*>(resid)[(size_t)v * (CDIM / 4) + c4] = r;
}

// ---------------------------------------------------------------------------
// GEMM:  D[M, Nc] = A[M, K] @ W[Nc, K]^T + bias[Nc]   (optional ReLU)
// 64x64 tile, BK=16, 256 threads, 4x4 register blocking.
// M % 64 == 0, Nc % 64 == 0, K % 16 == 0 (true for all shapes here).
// ---------------------------------------------------------------------------
#define BM 64
#define BN 64
#define BKK 16

template <bool RELU>
__global__ void gemm_bias_kernel(const float* __restrict__ A,
                                 const float* __restrict__ W,
                                 const float* __restrict__ bias,
                                 float* __restrict__ D,
                                 int M, int Nc, int K) {
    __shared__ float As[BKK][BM + 1];
    __shared__ float Ws[BKK][BN + 1];
    int tid = threadIdx.x;            // 0..255
    int tx = tid & 15;                // 0..15
    int ty = tid >> 4;                // 0..15
    int m0 = blockIdx.y * BM;
    int n0 = blockIdx.x * BN;
    int lm = tid >> 2;                // 0..63 (row within tile for loads)
    int lk = (tid & 3) * 4;           // 0,4,8,12

    float acc[4][4];
#pragma unroll
    for (int i = 0; i < 4; i++)
#pragma unroll
        for (int j = 0; j < 4; j++) acc[i][j] = 0.f;

    for (int k0 = 0; k0 < K; k0 += BKK) {
        float4 a4 = *reinterpret_cast<const float4*>(A + (size_t)(m0 + lm) * K + k0 + lk);
        float4 w4 = *reinterpret_cast<const float4*>(W + (size_t)(n0 + lm) * K + k0 + lk);
        As[lk + 0][lm] = a4.x; As[lk + 1][lm] = a4.y;
        As[lk + 2][lm] = a4.z; As[lk + 3][lm] = a4.w;
        Ws[lk + 0][lm] = w4.x; Ws[lk + 1][lm] = w4.y;
        Ws[lk + 2][lm] = w4.z; Ws[lk + 3][lm] = w4.w;
        __syncthreads();
#pragma unroll
        for (int kk = 0; kk < BKK; kk++) {
            float a[4], b[4];
#pragma unroll
            for (int i = 0; i < 4; i++) a[i] = As[kk][ty * 4 + i];
#pragma unroll
            for (int j = 0; j < 4; j++) b[j] = Ws[kk][tx * 4 + j];
#pragma unroll
            for (int i = 0; i < 4; i++)
#pragma unroll
                for (int j = 0; j < 4; j++) acc[i][j] += a[i] * b[j];
        }
        __syncthreads();
    }

#pragma unroll
    for (int i = 0; i < 4; i++) {
        int m = m0 + ty * 4 + i;
#pragma unroll
        for (int j = 0; j < 4; j++) {
            int n = n0 + tx * 4 + j;
            float v = acc[i][j] + bias[n];
            if (RELU) v = fmaxf(v, 0.f);
            D[(size_t)m * Nc + n] = v;
        }
    }
}

// ---------------------------------------------------------------------------
// Attention: one block per set (4096 blocks), 288 threads = (36 rows x 8 heads).
// q,k,v for the set staged in dynamic smem (3 * 36 * 192 floats = 82944 B).
// Masks are all-false in this problem -> no masking.
// ---------------------------------------------------------------------------
__global__ void attn_kernel(const float* __restrict__ q,
                            const float* __restrict__ k,
                            const float* __restrict__ v,
                            float* __restrict__ o) {
    extern __shared__ float sm[];
    float* qs = sm;
    float* ks = sm + SETSZ * CDIM;
    float* vs = sm + 2 * SETSZ * CDIM;
    int s = blockIdx.x;
    size_t base = (size_t)s * SETSZ * CDIM;
    int tid = threadIdx.x;  // 0..287

    const int NV4 = SETSZ * CDIM / 4;  // 1728
    const float4* q4 = reinterpret_cast<const float4*>(q + base);
    const float4* k4 = reinterpret_cast<const float4*>(k + base);
    const float4* v4 = reinterpret_cast<const float4*>(v + base);
    for (int idx = tid; idx < NV4; idx += 288) {
        reinterpret_cast<float4*>(qs)[idx] = q4[idx];
        reinterpret_cast<float4*>(ks)[idx] = k4[idx];
        reinterpret_cast<float4*>(vs)[idx] = v4[idx];
    }
    __syncthreads();

    int l = tid % SETSZ;   // row
    int h = tid / SETSZ;   // head 0..7

    float qr[DH];
#pragma unroll
    for (int d = 0; d < DH; d++) qr[d] = qs[l * CDIM + h * DH + d];

    const float scale = 0.20412414523193154f;  // 1/sqrt(24)
    float sc[SETSZ];
    float mx = -1e30f;
#pragma unroll 4
    for (int m = 0; m < SETSZ; m++) {
        const float* kr = ks + m * CDIM + h * DH;
        float dot = 0.f;
#pragma unroll
        for (int d = 0; d < DH; d++) dot += qr[d] * kr[d];
        dot *= scale;
        sc[m] = dot;
        mx = fmaxf(mx, dot);
    }
    float sum = 0.f;
#pragma unroll 4
    for (int m = 0; m < SETSZ; m++) {
        sc[m] = expf(sc[m] - mx);
        sum += sc[m];
    }
    float inv = 1.0f / sum;
#pragma unroll
    for (int d = 0; d < DH; d++) {
        float acc = 0.f;
#pragma unroll 4
        for (int m = 0; m < SETSZ; m++) acc += sc[m] * vs[m * CDIM + h * DH + d];
        o[base + l * CDIM + h * DH + d] = acc * inv;
    }
}

// ---------------------------------------------------------------------------
// LayerNorm over C=192: one block per row, 192 threads.
// out = LN(a + (b ? b : 0)) * w + bias.   b may be the same buffer as out
// (each thread reads before any thread of this block writes its element; the
// read happens before __syncthreads and writes come after full reduction).
// ---------------------------------------------------------------------------
__global__ void ln_kernel(const float* __restrict__ a,
                          const float* __restrict__ b,
                          const float* __restrict__ w,
                          const float* __restrict__ bias,
                          float* __restrict__ outp) {
    int row = blockIdx.x;
    int c = threadIdx.x;  // 0..191
    size_t idx = (size_t)row * CDIM + c;
    float v = a[idx];
    if (b) v += b[idx];

    float s = v, s2 = v * v;
#pragma unroll
    for (int off = 16; off > 0; off >>= 1) {
        s += __shfl_down_sync(0xffffffffu, s, off);
        s2 += __shfl_down_sync(0xffffffffu, s2, off);
    }
    __shared__ float ws[6], ws2[6];
    int wid = c >> 5, lane = c & 31;
    if (lane == 0) { ws[wid] = s; ws2[wid] = s2; }
    __syncthreads();
    float tot = 0.f, tot2 = 0.f;
#pragma unroll
    for (int i = 0; i < 6; i++) { tot += ws[i]; tot2 += ws2[i]; }
    float mean = tot * (1.0f / CDIM);
    float var = tot2 * (1.0f / CDIM) - mean * mean;
    float r = rsqrtf(var + 1e-5f);
    outp[idx] = (v - mean) * r * w[c] + bias[c];
}

// ---------------------------------------------------------------------------
// Host orchestration
// ---------------------------------------------------------------------------
extern "C" void kernel_launch(void* const* d_in, const int* in_sizes, int n_in,
                              void* d_out, int out_size) {
    (void)in_sizes; (void)n_in; (void)out_size;
    const float* src  = (const float*)d_in[0];
    const int*   inds = (const int*)d_in[1];
    // d_in[2]: masks (all false) — unused
    const float* pos  = (const float*)d_in[3];
    const int*   bid  = (const int*)d_in[4];
    const float* ipw  = (const float*)d_in[5];   // (2, 3C, C)
    const float* ipb  = (const float*)d_in[6];   // (2, 3C)
    const float* opw  = (const float*)d_in[7];   // (2, C, C)
    const float* opb  = (const float*)d_in[8];   // (2, C)
    const float* l1w  = (const float*)d_in[9];   // (2, DFF, C)
    const float* l1b  = (const float*)d_in[10];  // (2, DFF)
    const float* l2w  = (const float*)d_in[11];  // (2, C, DFF)
    const float* l2b  = (const float*)d_in[12];  // (2, C)
    const float* n1w  = (const float*)d_in[13];
    const float* n1b  = (const float*)d_in[14];
    const float* n2w  = (const float*)d_in[15];
    const float* n2b  = (const float*)d_in[16];
    const float* n3w  = (const float*)d_in[17];
    const float* n3b  = (const float*)d_in[18];

    float* out = (float*)d_out;

    float *bufA, *bufB, *bufC, *bufD, *bufE, *bufH;
    cudaGetSymbolAddress((void**)&bufA, g_bufA);
    cudaGetSymbolAddress((void**)&bufB, g_bufB);
    cudaGetSymbolAddress((void**)&bufC, g_bufC);
    cudaGetSymbolAddress((void**)&bufD, g_bufD);
    cudaGetSymbolAddress((void**)&bufE, g_bufE);
    cudaGetSymbolAddress((void**)&bufH, g_bufH);

    const int attn_smem = 3 * SETSZ * CDIM * (int)sizeof(float);  // 82944
    cudaFuncSetAttribute(attn_kernel, cudaFuncAttributeMaxDynamicSharedMemorySize, attn_smem);

    // output starts as src
    cudaMemcpyAsync(out, src, (size_t)NVOX * CDIM * sizeof(float),
                    cudaMemcpyDeviceToDevice, 0);

    const int TOT4 = NVOX * (CDIM / 4);
    dim3 gthr(256);
    dim3 ggrid((TOT4 + 255) / 256);
    dim3 gblk(256);
    dim3 grid192(CDIM / BN, NVOX / BM);
    dim3 grid768(DFF / BN, NVOX / BM);

    for (int i = 0; i < 2; i++) {
        const float* Wq = ipw + (size_t)i * 3 * CDIM * CDIM;
        const float* Wk = Wq + CDIM * CDIM;
        const float* Wv = Wk + CDIM * CDIM;
        const float* bq = ipb + (size_t)i * 3 * CDIM;
        const float* bk = bq + CDIM;
        const float* bv = bk + CDIM;
        const float* posL = pos + (size_t)i * NVOX * CDIM;

        // 1. gather: bufA = q_in (feat+pos), bufB = feat
        gather_kernel<<<ggrid, gthr>>>(out, posL, inds, bid, i, bufA, bufB);

        // 2. QKV projections
        gemm_bias_kernel<false><<<grid192, gblk>>>(bufA, Wq, bq, bufC, NVOX, CDIM, CDIM);
        gemm_bias_kernel<false><<<grid192, gblk>>>(bufA, Wk, bk, bufD, NVOX, CDIM, CDIM);
        gemm_bias_kernel<false><<<grid192, gblk>>>(bufB, Wv, bv, bufE, NVOX, CDIM, CDIM);

        // 3. attention -> bufA (overwrites q_in, which is no longer needed)
        attn_kernel<<<NSET, 288, attn_smem>>>(bufC, bufD, bufE, bufA);

        // 4. out_proj -> bufB
        gemm_bias_kernel<false><<<grid192, gblk>>>(
            bufA, opw + (size_t)i * CDIM * CDIM, opb + (size_t)i * CDIM,
            bufB, NVOX, CDIM, CDIM);

        // 5. scatter + residual -> bufC (voxel order)
        scatter_kernel<<<ggrid, gthr>>>(out, bufB, inds, bid, i, bufC);

        // 6. norm1 -> bufD  (x)
        ln_kernel<<<NVOX, CDIM>>>(bufC, nullptr, n1w + i * CDIM, n1b + i * CDIM, bufD);

        // 7. FFN lin1 + relu -> bufH (N x 768)
        gemm_bias_kernel<true><<<grid768, gblk>>>(
            bufD, l1w + (size_t)i * DFF * CDIM, l1b + (size_t)i * DFF,
            bufH, NVOX, DFF, CDIM);

        // 8. FFN lin2 -> bufE
        gemm_bias_kernel<false><<<grid192, gblk>>>(
            bufH, l2w + (size_t)i * CDIM * DFF, l2b + (size_t)i * CDIM,
            bufE, NVOX, CDIM, DFF);

        // 9. norm2: LN(x + ffn) -> bufC
        ln_kernel<<<NVOX, CDIM>>>(bufD, bufE, n2w + i * CDIM, n2b + i * CDIM, bufC);

        // 10. norm3: LN(x2 + identity) -> out (in place: b aliases out, safe)
        ln_kernel<<<NVOX, CDIM>>>(bufC, out, n3w + i * CDIM, n3b + i * CDIM, out);
    }
}

// round 2
// speedup vs baseline: 1.8297x; 1.8297x over previous
#include <cuda_runtime.h>
#include <cuda_bf16.h>
#include <math.h>

// Problem constants
#define NVOX 147456
#define CDIM 192
#define NH 8
#define DH 24
#define DFF 768
#define SETSZ 36
#define NSET 4096

// ---------------------------------------------------------------------------
// Scratch buffers (device globals; allocation-free per harness rules)
// ---------------------------------------------------------------------------
__device__ float g_bufA[(size_t)NVOX * CDIM];
__device__ float g_bufB[(size_t)NVOX * CDIM];
__device__ float g_bufC[(size_t)NVOX * CDIM];
__device__ float g_bufD[(size_t)NVOX * CDIM];
__device__ float g_bufE[(size_t)NVOX * CDIM];
__device__ float g_bufH[(size_t)NVOX * DFF];

// ---------------------------------------------------------------------------
// Gather
// ---------------------------------------------------------------------------
__global__ void gather_kernel(const float* __restrict__ out,
                              const float* __restrict__ pos,
                              const int* __restrict__ inds_all,
                              const int* __restrict__ block_id,
                              int layer,
                              float* __restrict__ g,
                              float* __restrict__ sfb) {
    int gid = blockIdx.x * blockDim.x + threadIdx.x;
    const int TOT = NVOX * (CDIM / 4);
    if (gid >= TOT) return;
    int p = gid / (CDIM / 4);
    int c4 = gid % (CDIM / 4);
    int shift = block_id[0] & 1;
    const int* inds = inds_all + ((size_t)shift * 2 + layer) * NVOX;
    int v = inds[p];
    float4 f = reinterpret_cast<const float4*>(out)[(size_t)v * (CDIM / 4) + c4];
    float4 pp = reinterpret_cast<const float4*>(pos)[(size_t)v * (CDIM / 4) + c4];
    reinterpret_cast<float4*>(sfb)[gid] = f;
    float4 r;
    r.x = f.x + pp.x; r.y = f.y + pp.y; r.z = f.z + pp.z; r.w = f.w + pp.w;
    reinterpret_cast<float4*>(g)[gid] = r;
}

// ---------------------------------------------------------------------------
// Scatter + residual
// ---------------------------------------------------------------------------
__global__ void scatter_kernel(const float* __restrict__ out,
                               const float* __restrict__ oproj,
                               const int* __restrict__ inds_all,
                               const int* __restrict__ block_id,
                               int layer,
                               float* __restrict__ resid) {
    int gid = blockIdx.x * blockDim.x + threadIdx.x;
    const int TOT = NVOX * (CDIM / 4);
    if (gid >= TOT) return;
    int p = gid / (CDIM / 4);
    int c4 = gid % (CDIM / 4);
    int shift = block_id[0] & 1;
    const int* inds = inds_all + ((size_t)shift * 2 + layer) * NVOX;
    int v = inds[p];
    float4 a = reinterpret_cast<const float4*>(out)[(size_t)v * (CDIM / 4) + c4];
    float4 b = reinterpret_cast<const float4*>(oproj)[gid];
    float4 r;
    r.x = a.x + b.x; r.y = a.y + b.y; r.z = a.z + b.z; r.w = a.w + b.w;
    reinterpret_cast<float4*>(resid)[(size_t)v * (CDIM / 4) + c4] = r;
}

// ---------------------------------------------------------------------------
// TF32 tensor-core GEMM:  D[M, Nc] = A[M, K] @ W[Nc, K]^T + bias  (opt ReLU)
// Tile 128x64x32, 256 threads (8 warps, 4(m) x 2(n)), warp tile 32x32 via
// mma.sync.m16n8k8.tf32. M%128==0, Nc%64==0, K%32==0 for all shapes here.
// ---------------------------------------------------------------------------
#define BMt 128
#define BNt 64
#define BKt 32

__device__ __forceinline__ unsigned f2tf32(float x) {
    unsigned r;
    asm("cvt.rna.tf32.f32 %0, %1;" : "=r"(r) : "f"(x));
    return r;
}

__device__ __forceinline__ void mma_tf32(float c[4], const unsigned a[4], const unsigned b[2]) {
    asm volatile(
        "mma.sync.aligned.m16n8k8.row.col.f32.tf32.tf32.f32 "
        "{%0,%1,%2,%3},{%4,%5,%6,%7},{%8,%9},{%0,%1,%2,%3};"
        : "+f"(c[0]), "+f"(c[1]), "+f"(c[2]), "+f"(c[3])
        : "r"(a[0]), "r"(a[1]), "r"(a[2]), "r"(a[3]), "r"(b[0]), "r"(b[1]));
}

template <bool RELU>
__global__ __launch_bounds__(256) void gemm_tf32_kernel(
        const float* __restrict__ A,
        const float* __restrict__ W,
        const float* __restrict__ bias,
        float* __restrict__ D,
        int M, int Nc, int K) {
    __shared__ unsigned As[BKt][BMt + 4];
    __shared__ unsigned Ws[BKt][BNt + 4];

    const int tid = threadIdx.x;
    const int lane = tid & 31;
    const int wid = tid >> 5;
    const int wm = (wid & 3) * 32;   // warp m offset within tile
    const int wn = (wid >> 2) * 32;  // warp n offset within tile
    const int m0 = blockIdx.y * BMt;
    const int n0 = blockIdx.x * BNt;

    float acc[2][4][4];
#pragma unroll
    for (int mt = 0; mt < 2; mt++)
#pragma unroll
        for (int nt = 0; nt < 4; nt++)
#pragma unroll
            for (int r = 0; r < 4; r++) acc[mt][nt][r] = 0.f;

    const int gid = lane >> 2;   // 0..7
    const int tig = lane & 3;    // 0..3

    for (int k0 = 0; k0 < K; k0 += BKt) {
        // Load A tile (128x32): 1024 float4, 4 per thread
#pragma unroll
        for (int i = 0; i < 4; i++) {
            int idx = i * 256 + tid;
            int r = idx >> 3;
            int c4 = (idx & 7) * 4;
            float4 v = *reinterpret_cast<const float4*>(A + (size_t)(m0 + r) * K + k0 + c4);
            As[c4 + 0][r] = f2tf32(v.x);
            As[c4 + 1][r] = f2tf32(v.y);
            As[c4 + 2][r] = f2tf32(v.z);
            As[c4 + 3][r] = f2tf32(v.w);
        }
        // Load W tile (64x32): 512 float4, 2 per thread
#pragma unroll
        for (int i = 0; i < 2; i++) {
            int idx = i * 256 + tid;
            int r = idx >> 3;
            int c4 = (idx & 7) * 4;
            float4 v = *reinterpret_cast<const float4*>(W + (size_t)(n0 + r) * K + k0 + c4);
            Ws[c4 + 0][r] = f2tf32(v.x);
            Ws[c4 + 1][r] = f2tf32(v.y);
            Ws[c4 + 2][r] = f2tf32(v.z);
            Ws[c4 + 3][r] = f2tf32(v.w);
        }
        __syncthreads();

#pragma unroll
        for (int ks = 0; ks < 4; ks++) {
            const int kb = ks * 8 + tig;
            unsigned af[2][4], bf[4][2];
#pragma unroll
            for (int mt = 0; mt < 2; mt++) {
                int mr = wm + mt * 16 + gid;
                af[mt][0] = As[kb][mr];
                af[mt][1] = As[kb][mr + 8];
                af[mt][2] = As[kb + 4][mr];
                af[mt][3] = As[kb + 4][mr + 8];
            }
#pragma unroll
            for (int nt = 0; nt < 4; nt++) {
                int nr = wn + nt * 8 + gid;
                bf[nt][0] = Ws[kb][nr];
                bf[nt][1] = Ws[kb + 4][nr];
            }
#pragma unroll
            for (int mt = 0; mt < 2; mt++)
#pragma unroll
                for (int nt = 0; nt < 4; nt++)
                    mma_tf32(acc[mt][nt], af[mt], bf[nt]);
        }
        __syncthreads();
    }

    // Epilogue: bias (+relu), float2 stores
#pragma unroll
    for (int mt = 0; mt < 2; mt++) {
#pragma unroll
        for (int nt = 0; nt < 4; nt++) {
            int m = m0 + wm + mt * 16 + gid;
            int n = n0 + wn + nt * 8 + tig * 2;
            float b0 = bias[n], b1 = bias[n + 1];
            float v0 = acc[mt][nt][0] + b0;
            float v1 = acc[mt][nt][1] + b1;
            float v2 = acc[mt][nt][2] + b0;
            float v3 = acc[mt][nt][3] + b1;
            if (RELU) {
                v0 = fmaxf(v0, 0.f); v1 = fmaxf(v1, 0.f);
                v2 = fmaxf(v2, 0.f); v3 = fmaxf(v3, 0.f);
            }
            *reinterpret_cast<float2*>(D + (size_t)m * Nc + n) = make_float2(v0, v1);
            *reinterpret_cast<float2*>(D + (size_t)(m + 8) * Nc + n) = make_float2(v2, v3);
        }
    }
}

// ---------------------------------------------------------------------------
// Attention: one block per set, 288 threads = (36 rows x 8 heads)
// ---------------------------------------------------------------------------
__global__ void attn_kernel(const float* __restrict__ q,
                            const float* __restrict__ k,
                            const float* __restrict__ v,
                            float* __restrict__ o) {
    extern __shared__ float sm[];
    float* qs = sm;
    float* ks = sm + SETSZ * CDIM;
    float* vs = sm + 2 * SETSZ * CDIM;
    int s = blockIdx.x;
    size_t base = (size_t)s * SETSZ * CDIM;
    int tid = threadIdx.x;

    const int NV4 = SETSZ * CDIM / 4;
    const float4* q4 = reinterpret_cast<const float4*>(q + base);
    const float4* k4 = reinterpret_cast<const float4*>(k + base);
    const float4* v4 = reinterpret_cast<const float4*>(v + base);
    for (int idx = tid; idx < NV4; idx += 288) {
        reinterpret_cast<float4*>(qs)[idx] = q4[idx];
        reinterpret_cast<float4*>(ks)[idx] = k4[idx];
        reinterpret_cast<float4*>(vs)[idx] = v4[idx];
    }
    __syncthreads();

    int l = tid % SETSZ;
    int h = tid / SETSZ;

    float qr[DH];
#pragma unroll
    for (int d = 0; d < DH; d++) qr[d] = qs[l * CDIM + h * DH + d];

    const float scale = 0.20412414523193154f;
    float sc[SETSZ];
    float mx = -1e30f;
#pragma unroll 4
    for (int m = 0; m < SETSZ; m++) {
        const float* kr = ks + m * CDIM + h * DH;
        float dot = 0.f;
#pragma unroll
        for (int d = 0; d < DH; d++) dot += qr[d] * kr[d];
        dot *= scale;
        sc[m] = dot;
        mx = fmaxf(mx, dot);
    }
    float sum = 0.f;
#pragma unroll 4
    for (int m = 0; m < SETSZ; m++) {
        sc[m] = expf(sc[m] - mx);
        sum += sc[m];
    }
    float inv = 1.0f / sum;
#pragma unroll
    for (int d = 0; d < DH; d++) {
        float acc = 0.f;
#pragma unroll 4
        for (int m = 0; m < SETSZ; m++) acc += sc[m] * vs[m * CDIM + h * DH + d];
        o[base + l * CDIM + h * DH + d] = acc * inv;
    }
}

// ---------------------------------------------------------------------------
// LayerNorm over C=192: one block per row, 192 threads
// ---------------------------------------------------------------------------
__global__ void ln_kernel(const float* __restrict__ a,
                          const float* __restrict__ b,
                          const float* __restrict__ w,
                          const float* __restrict__ bias,
                          float* __restrict__ outp) {
    int row = blockIdx.x;
    int c = threadIdx.x;
    size_t idx = (size_t)row * CDIM + c;
    float v = a[idx];
    if (b) v += b[idx];

    float s = v, s2 = v * v;
#pragma unroll
    for (int off = 16; off > 0; off >>= 1) {
        s += __shfl_down_sync(0xffffffffu, s, off);
        s2 += __shfl_down_sync(0xffffffffu, s2, off);
    }
    __shared__ float ws[6], ws2[6];
    int wid = c >> 5, lane = c & 31;
    if (lane == 0) { ws[wid] = s; ws2[wid] = s2; }
    __syncthreads();
    float tot = 0.f, tot2 = 0.f;
#pragma unroll
    for (int i = 0; i < 6; i++) { tot += ws[i]; tot2 += ws2[i]; }
    float mean = tot * (1.0f / CDIM);
    float var = tot2 * (1.0f / CDIM) - mean * mean;
    float r = rsqrtf(var + 1e-5f);
    outp[idx] = (v - mean) * r * w[c] + bias[c];
}

// ---------------------------------------------------------------------------
// Host orchestration
// ---------------------------------------------------------------------------
extern "C" void kernel_launch(void* const* d_in, const int* in_sizes, int n_in,
                              void* d_out, int out_size) {
    (void)in_sizes; (void)n_in; (void)out_size;
    const float* src  = (const float*)d_in[0];
    const int*   inds = (const int*)d_in[1];
    const float* pos  = (const float*)d_in[3];
    const int*   bid  = (const int*)d_in[4];
    const float* ipw  = (const float*)d_in[5];
    const float* ipb  = (const float*)d_in[6];
    const float* opw  = (const float*)d_in[7];
    const float* opb  = (const float*)d_in[8];
    const float* l1w  = (const float*)d_in[9];
    const float* l1b  = (const float*)d_in[10];
    const float* l2w  = (const float*)d_in[11];
    const float* l2b  = (const float*)d_in[12];
    const float* n1w  = (const float*)d_in[13];
    const float* n1b  = (const float*)d_in[14];
    const float* n2w  = (const float*)d_in[15];
    const float* n2b  = (const float*)d_in[16];
    const float* n3w  = (const float*)d_in[17];
    const float* n3b  = (const float*)d_in[18];

    float* out = (float*)d_out;

    float *bufA, *bufB, *bufC, *bufD, *bufE, *bufH;
    cudaGetSymbolAddress((void**)&bufA, g_bufA);
    cudaGetSymbolAddress((void**)&bufB, g_bufB);
    cudaGetSymbolAddress((void**)&bufC, g_bufC);
    cudaGetSymbolAddress((void**)&bufD, g_bufD);
    cudaGetSymbolAddress((void**)&bufE, g_bufE);
    cudaGetSymbolAddress((void**)&bufH, g_bufH);

    const int attn_smem = 3 * SETSZ * CDIM * (int)sizeof(float);
    cudaFuncSetAttribute(attn_kernel, cudaFuncAttributeMaxDynamicSharedMemorySize, attn_smem);

    const int TOT4 = NVOX * (CDIM / 4);
    dim3 gthr(256);
    dim3 ggrid((TOT4 + 255) / 256);
    dim3 gblk(256);
    dim3 grid192(CDIM / BNt, NVOX / BMt);
    dim3 grid768(DFF / BNt, NVOX / BMt);

    for (int i = 0; i < 2; i++) {
        const float* Wq = ipw + (size_t)i * 3 * CDIM * CDIM;
        const float* Wk = Wq + CDIM * CDIM;
        const float* Wv = Wk + CDIM * CDIM;
        const float* bq = ipb + (size_t)i * 3 * CDIM;
        const float* bk = bq + CDIM;
        const float* bv = bk + CDIM;
        const float* posL = pos + (size_t)i * NVOX * CDIM;
        const float* cur = (i == 0) ? src : out;  // layer input / identity

        // 1. gather: bufA = feat+pos, bufB = feat
        gather_kernel<<<ggrid, gthr>>>(cur, posL, inds, bid, i, bufA, bufB);

        // 2. QKV projections (tf32 tensor cores)
        gemm_tf32_kernel<false><<<grid192, gblk>>>(bufA, Wq, bq, bufC, NVOX, CDIM, CDIM);
        gemm_tf32_kernel<false><<<grid192, gblk>>>(bufA, Wk, bk, bufD, NVOX, CDIM, CDIM);
        gemm_tf32_kernel<false><<<grid192, gblk>>>(bufB, Wv, bv, bufE, NVOX, CDIM, CDIM);

        // 3. attention -> bufA
        attn_kernel<<<NSET, 288, attn_smem>>>(bufC, bufD, bufE, bufA);

        // 4. out_proj -> bufB
        gemm_tf32_kernel<false><<<grid192, gblk>>>(
            bufA, opw + (size_t)i * CDIM * CDIM, opb + (size_t)i * CDIM,
            bufB, NVOX, CDIM, CDIM);

        // 5. scatter + residual -> bufC
        scatter_kernel<<<ggrid, gthr>>>(cur, bufB, inds, bid, i, bufC);

        // 6. norm1 -> bufD
        ln_kernel<<<NVOX, CDIM>>>(bufC, nullptr, n1w + i * CDIM, n1b + i * CDIM, bufD);

        // 7. FFN lin1 + relu -> bufH
        gemm_tf32_kernel<true><<<grid768, gblk>>>(
            bufD, l1w + (size_t)i * DFF * CDIM, l1b + (size_t)i * DFF,
            bufH, NVOX, DFF, CDIM);

        // 8. FFN lin2 -> bufE
        gemm_tf32_kernel<false><<<grid192, gblk>>>(
            bufH, l2w + (size_t)i * CDIM * DFF, l2b + (size_t)i * CDIM,
            bufE, NVOX, CDIM, DFF);

        // 9. norm2: LN(x + ffn) -> bufC
        ln_kernel<<<NVOX, CDIM>>>(bufD, bufE, n2w + i * CDIM, n2b + i * CDIM, bufC);

        // 10. norm3: LN(x2 + identity) -> out
        ln_kernel<<<NVOX, CDIM>>>(bufC, cur, n3w + i * CDIM, n3b + i * CDIM, out);
    }
}

// round 3
// speedup vs baseline: 4.6249x; 2.5276x over previous
#include <cuda_runtime.h>
#include <cuda_bf16.h>
#include <math.h>
#include <stdint.h>

// Problem constants
#define NVOX 147456
#define CDIM 192
#define NH 8
#define DH 24
#define DFF 768
#define SETSZ 36
#define NSET 4096

// ---------------------------------------------------------------------------
// Scratch (device globals; allocation-free)
// ---------------------------------------------------------------------------
__device__ float g_f32B[(size_t)NVOX * CDIM];   // out_proj output
__device__ float g_f32C[(size_t)NVOX * CDIM];   // scatter out / norm2 out
__device__ float g_f32D[(size_t)NVOX * CDIM];   // x (post-norm1, fp32)
__device__ float g_f32E[(size_t)NVOX * CDIM];   // lin2 out
__device__ __nv_bfloat16 g_qin16[(size_t)NVOX * CDIM];   // q_in / attn-out
__device__ __nv_bfloat16 g_feat16[(size_t)NVOX * CDIM];
__device__ __nv_bfloat16 g_q16[(size_t)NVOX * CDIM];
__device__ __nv_bfloat16 g_k16[(size_t)NVOX * CDIM];
__device__ __nv_bfloat16 g_v16[(size_t)NVOX * CDIM];
__device__ __nv_bfloat16 g_x16[(size_t)NVOX * CDIM];
__device__ __nv_bfloat16 g_h16[(size_t)NVOX * DFF];
// bf16 weights: [ipw | opw | l1w | l2w]
#define IPW_OFF 0
#define OPW_OFF 221184
#define L1W_OFF 294912
#define L2W_OFF 589824
__device__ __nv_bfloat16 g_w16[884736];

// ---------------------------------------------------------------------------
// fp32 -> bf16 converter (weights)
// ---------------------------------------------------------------------------
__global__ void cvt_kernel(const float* __restrict__ src, __nv_bfloat16* __restrict__ dst, int n4) {
    int i = blockIdx.x * blockDim.x + threadIdx.x;
    if (i >= n4) return;
    float4 v = reinterpret_cast<const float4*>(src)[i];
    reinterpret_cast<__nv_bfloat162*>(dst)[i * 2 + 0] = __floats2bfloat162_rn(v.x, v.y);
    reinterpret_cast<__nv_bfloat162*>(dst)[i * 2 + 1] = __floats2bfloat162_rn(v.z, v.w);
}

// ---------------------------------------------------------------------------
// Gather: qin16[p] = bf16(cur[v] + pos[v]); feat16[p] = bf16(cur[v])
// ---------------------------------------------------------------------------
__global__ void gather_kernel(const float* __restrict__ cur,
                              const float* __restrict__ pos,
                              const int* __restrict__ inds_all,
                              const int* __restrict__ block_id,
                              int layer,
                              __nv_bfloat16* __restrict__ qin,
                              __nv_bfloat16* __restrict__ feat) {
    int gid = blockIdx.x * blockDim.x + threadIdx.x;
    const int TOT = NVOX * (CDIM / 4);
    if (gid >= TOT) return;
    int p = gid / (CDIM / 4);
    int c4 = gid % (CDIM / 4);
    int shift = block_id[0] & 1;
    const int* inds = inds_all + ((size_t)shift * 2 + layer) * NVOX;
    int v = inds[p];
    float4 f = reinterpret_cast<const float4*>(cur)[(size_t)v * (CDIM / 4) + c4];
    float4 pp = reinterpret_cast<const float4*>(pos)[(size_t)v * (CDIM / 4) + c4];
    __nv_bfloat162* f2 = reinterpret_cast<__nv_bfloat162*>(feat);
    __nv_bfloat162* q2 = reinterpret_cast<__nv_bfloat162*>(qin);
    f2[gid * 2 + 0] = __floats2bfloat162_rn(f.x, f.y);
    f2[gid * 2 + 1] = __floats2bfloat162_rn(f.z, f.w);
    q2[gid * 2 + 0] = __floats2bfloat162_rn(f.x + pp.x, f.y + pp.y);
    q2[gid * 2 + 1] = __floats2bfloat162_rn(f.z + pp.z, f.w + pp.w);
}

// ---------------------------------------------------------------------------
// Scatter + residual (fp32): resid[v] = cur[v] + oproj[p]
// ---------------------------------------------------------------------------
__global__ void scatter_kernel(const float* __restrict__ cur,
                               const float* __restrict__ oproj,
                               const int* __restrict__ inds_all,
                               const int* __restrict__ block_id,
                               int layer,
                               float* __restrict__ resid) {
    int gid = blockIdx.x * blockDim.x + threadIdx.x;
    const int TOT = NVOX * (CDIM / 4);
    if (gid >= TOT) return;
    int p = gid / (CDIM / 4);
    int c4 = gid % (CDIM / 4);
    int shift = block_id[0] & 1;
    const int* inds = inds_all + ((size_t)shift * 2 + layer) * NVOX;
    int v = inds[p];
    float4 a = reinterpret_cast<const float4*>(cur)[(size_t)v * (CDIM / 4) + c4];
    float4 b = reinterpret_cast<const float4*>(oproj)[gid];
    float4 r;
    r.x = a.x + b.x; r.y = a.y + b.y; r.z = a.z + b.z; r.w = a.w + b.w;
    reinterpret_cast<float4*>(resid)[(size_t)v * (CDIM / 4) + c4] = r;
}

// ---------------------------------------------------------------------------
// bf16 tensor-core GEMM: D[M,Nc] = A[M,K] @ W[Nc,K]^T + bias (opt ReLU)
// Tile 128x64x32, 256 thr (8 warps 4m x 2n, warp tile 32x32),
// mma.m16n8k16.bf16, ldmatrix fragments, cp.async double buffering.
// ---------------------------------------------------------------------------
__device__ __forceinline__ void cp16(uint32_t dst, const void* src) {
    asm volatile("cp.async.cg.shared.global [%0], [%1], 16;\n" :: "r"(dst), "l"(src));
}
__device__ __forceinline__ void ldsm4(uint32_t* r, uint32_t addr) {
    asm volatile("ldmatrix.sync.aligned.m8n8.x4.shared.b16 {%0,%1,%2,%3}, [%4];"
                 : "=r"(r[0]), "=r"(r[1]), "=r"(r[2]), "=r"(r[3]) : "r"(addr));
}
__device__ __forceinline__ void mma_bf16(float* c, const uint32_t* a, const uint32_t* b) {
    asm volatile(
        "mma.sync.aligned.m16n8k16.row.col.f32.bf16.bf16.f32 "
        "{%0,%1,%2,%3},{%4,%5,%6,%7},{%8,%9},{%0,%1,%2,%3};"
        : "+f"(c[0]), "+f"(c[1]), "+f"(c[2]), "+f"(c[3])
        : "r"(a[0]), "r"(a[1]), "r"(a[2]), "r"(a[3]), "r"(b[0]), "r"(b[1]));
}

template <typename OutT, bool RELU>
__global__ __launch_bounds__(256) void gemm_bf16_kernel(
        const __nv_bfloat16* __restrict__ A,
        const __nv_bfloat16* __restrict__ W,
        const float* __restrict__ bias,
        OutT* __restrict__ D,
        int M, int Nc, int K) {
    __shared__ alignas(16) unsigned char smA[2][128 * 64];  // 128 rows x 64B (32 bf16)
    __shared__ alignas(16) unsigned char smB[2][64 * 64];   // 64 rows x 64B

    const int tid = threadIdx.x;
    const int lane = tid & 31;
    const int wid = tid >> 5;
    const int wm = (wid & 3) * 32;
    const int wn = (wid >> 2) * 32;
    const int m0 = blockIdx.y * 128;
    const int n0 = blockIdx.x * 64;

    const uint32_t sA = (uint32_t)__cvta_generic_to_shared(smA);
    const uint32_t sB = (uint32_t)__cvta_generic_to_shared(smB);

    float acc[2][4][4];
#pragma unroll
    for (int mt = 0; mt < 2; mt++)
#pragma unroll
        for (int nt = 0; nt < 4; nt++)
#pragma unroll
            for (int r = 0; r < 4; r++) acc[mt][nt][r] = 0.f;

    auto stage = [&](int kt, int buf) {
        int k0 = kt * 32;
        // A tile: 512 16B chunks
#pragma unroll
        for (int i = 0; i < 2; i++) {
            int id = i * 256 + tid;
            int row = id >> 2, ch = id & 3;
            uint32_t dst = sA + buf * 8192 + row * 64 + ((ch ^ ((row >> 1) & 3)) * 16);
            cp16(dst, A + (size_t)(m0 + row) * K + k0 + ch * 8);
        }
        // W tile: 256 16B chunks
        {
            int row = tid >> 2, ch = tid & 3;
            uint32_t dst = sB + buf * 4096 + row * 64 + ((ch ^ ((row >> 1) & 3)) * 16);
            cp16(dst, W + (size_t)(n0 + row) * K + k0 + ch * 8);
        }
    };

    stage(0, 0);
    asm volatile("cp.async.commit_group;");

    const int nk = K / 32;
    for (int t = 0; t < nk; t++) {
        int buf = t & 1;
        if (t + 1 < nk) stage(t + 1, buf ^ 1);
        asm volatile("cp.async.commit_group;");
        asm volatile("cp.async.wait_group 1;");
        __syncthreads();

#pragma unroll
        for (int ks = 0; ks < 2; ks++) {
            uint32_t af[2][4], bf[4][2];
#pragma unroll
            for (int mt = 0; mt < 2; mt++) {
                int row = wm + mt * 16 + (lane & 15);
                int ch = ks * 2 + (lane >> 4);
                uint32_t addr = sA + buf * 8192 + row * 64 + ((ch ^ ((row >> 1) & 3)) * 16);
                ldsm4(af[mt], addr);
            }
#pragma unroll
            for (int p = 0; p < 2; p++) {
                int row = wn + p * 16 + ((lane >> 4) << 3) + (lane & 7);
                int ch = ks * 2 + ((lane >> 3) & 1);
                uint32_t addr = sB + buf * 4096 + row * 64 + ((ch ^ ((row >> 1) & 3)) * 16);
                uint32_t r4[4];
                ldsm4(r4, addr);
                bf[p * 2 + 0][0] = r4[0]; bf[p * 2 + 0][1] = r4[1];
                bf[p * 2 + 1][0] = r4[2]; bf[p * 2 + 1][1] = r4[3];
            }
#pragma unroll
            for (int mt = 0; mt < 2; mt++)
#pragma unroll
                for (int nt = 0; nt < 4; nt++)
                    mma_bf16(acc[mt][nt], af[mt], bf[nt]);
        }
        __syncthreads();
    }

    // Epilogue
#pragma unroll
    for (int mt = 0; mt < 2; mt++) {
#pragma unroll
        for (int nt = 0; nt < 4; nt++) {
            int m = m0 + wm + mt * 16 + (lane >> 2);
            int n = n0 + wn + nt * 8 + (lane & 3) * 2;
            float b0 = bias[n], b1 = bias[n + 1];
            float v0 = acc[mt][nt][0] + b0;
            float v1 = acc[mt][nt][1] + b1;
            float v2 = acc[mt][nt][2] + b0;
            float v3 = acc[mt][nt][3] + b1;
            if (RELU) {
                v0 = fmaxf(v0, 0.f); v1 = fmaxf(v1, 0.f);
                v2 = fmaxf(v2, 0.f); v3 = fmaxf(v3, 0.f);
            }
            if constexpr (sizeof(OutT) == 2) {
                __nv_bfloat162* d2a = reinterpret_cast<__nv_bfloat162*>((__nv_bfloat16*)D + (size_t)m * Nc + n);
                __nv_bfloat162* d2b = reinterpret_cast<__nv_bfloat162*>((__nv_bfloat16*)D + (size_t)(m + 8) * Nc + n);
                *d2a = __floats2bfloat162_rn(v0, v1);
                *d2b = __floats2bfloat162_rn(v2, v3);
            } else {
                *reinterpret_cast<float2*>((float*)D + (size_t)m * Nc + n) = make_float2(v0, v1);
                *reinterpret_cast<float2*>((float*)D + (size_t)(m + 8) * Nc + n) = make_float2(v2, v3);
            }
        }
    }
}

// ---------------------------------------------------------------------------
// Attention (bf16 in/out): one block per set, 288 threads = 36 rows x 8 heads
// ---------------------------------------------------------------------------
__global__ __launch_bounds__(288) void attn_kernel(const __nv_bfloat16* __restrict__ q,
                                                   const __nv_bfloat16* __restrict__ k,
                                                   const __nv_bfloat16* __restrict__ v,
                                                   __nv_bfloat16* __restrict__ o) {
    __shared__ __nv_bfloat16 qs[SETSZ * CDIM];
    __shared__ __nv_bfloat16 ks[SETSZ * CDIM];
    __shared__ __nv_bfloat16 vs[SETSZ * CDIM];
    int s = blockIdx.x;
    size_t base = (size_t)s * SETSZ * CDIM;
    int tid = threadIdx.x;

    const int NV8 = SETSZ * CDIM / 8;  // 864 16B chunks
    const uint4* q8 = reinterpret_cast<const uint4*>(q + base);
    const uint4* k8 = reinterpret_cast<const uint4*>(k + base);
    const uint4* v8 = reinterpret_cast<const uint4*>(v + base);
    for (int idx = tid; idx < NV8; idx += 288) {
        reinterpret_cast<uint4*>(qs)[idx] = q8[idx];
        reinterpret_cast<uint4*>(ks)[idx] = k8[idx];
        reinterpret_cast<uint4*>(vs)[idx] = v8[idx];
    }
    __syncthreads();

    int l = tid % SETSZ;
    int h = tid / SETSZ;

    float qr[DH];
#pragma unroll
    for (int d = 0; d < DH; d++) qr[d] = __bfloat162float(qs[l * CDIM + h * DH + d]);

    const float scale = 0.20412414523193154f;  // 1/sqrt(24)
    float sc[SETSZ];
    float mx = -1e30f;
#pragma unroll 4
    for (int m = 0; m < SETSZ; m++) {
        const __nv_bfloat16* kr = ks + m * CDIM + h * DH;
        float dot = 0.f;
#pragma unroll
        for (int d = 0; d < DH; d++) dot += qr[d] * __bfloat162float(kr[d]);
        dot *= scale;
        sc[m] = dot;
        mx = fmaxf(mx, dot);
    }
    float sum = 0.f;
#pragma unroll 4
    for (int m = 0; m < SETSZ; m++) {
        sc[m] = expf(sc[m] - mx);
        sum += sc[m];
    }
    float inv = 1.0f / sum;
    __nv_bfloat162* o2 = reinterpret_cast<__nv_bfloat162*>(o + base + l * CDIM + h * DH);
#pragma unroll
    for (int d2 = 0; d2 < DH / 2; d2++) {
        float a0 = 0.f, a1 = 0.f;
#pragma unroll 4
        for (int m = 0; m < SETSZ; m++) {
            float p = sc[m];
            a0 += p * __bfloat162float(vs[m * CDIM + h * DH + d2 * 2]);
            a1 += p * __bfloat162float(vs[m * CDIM + h * DH + d2 * 2 + 1]);
        }
        o2[d2] = __floats2bfloat162_rn(a0 * inv, a1 * inv);
    }
}

// ---------------------------------------------------------------------------
// LayerNorm, warp-per-row (8 rows/block). out = LN(a + b?) * w + bias.
// Optional bf16 copy of the output.
// ---------------------------------------------------------------------------
__global__ __launch_bounds__(256) void ln_kernel(const float* __restrict__ a,
                                                 const float* __restrict__ b,
                                                 const float* __restrict__ w,
                                                 const float* __restrict__ bias,
                                                 float* __restrict__ outp,
                                                 __nv_bfloat16* __restrict__ out16) {
    int warp = threadIdx.x >> 5, lane = threadIdx.x & 31;
    int row = blockIdx.x * 8 + warp;
    size_t base = (size_t)row * CDIM + lane * 6;

    float v[6];
    const float2* a2 = reinterpret_cast<const float2*>(a + base);
#pragma unroll
    for (int i = 0; i < 3; i++) {
        float2 t = a2[i];
        v[i * 2] = t.x; v[i * 2 + 1] = t.y;
    }
    if (b) {
        const float2* b2 = reinterpret_cast<const float2*>(b + base);
#pragma unroll
        for (int i = 0; i < 3; i++) {
            float2 t = b2[i];
            v[i * 2] += t.x; v[i * 2 + 1] += t.y;
        }
    }
    float s = 0.f, s2 = 0.f;
#pragma unroll
    for (int i = 0; i < 6; i++) { s += v[i]; s2 += v[i] * v[i]; }
#pragma unroll
    for (int off = 16; off > 0; off >>= 1) {
        s += __shfl_xor_sync(0xffffffffu, s, off);
        s2 += __shfl_xor_sync(0xffffffffu, s2, off);
    }
    float mean = s * (1.0f / CDIM);
    float var = s2 * (1.0f / CDIM) - mean * mean;
    float r = rsqrtf(var + 1e-5f);

    float o[6];
    const float2* w2 = reinterpret_cast<const float2*>(w + lane * 6);
    const float2* g2 = reinterpret_cast<const float2*>(bias + lane * 6);
#pragma unroll
    for (int i = 0; i < 3; i++) {
        float2 ww = w2[i], gg = g2[i];
        o[i * 2]     = (v[i * 2] - mean) * r * ww.x + gg.x;
        o[i * 2 + 1] = (v[i * 2 + 1] - mean) * r * ww.y + gg.y;
    }
    float2* d2 = reinterpret_cast<float2*>(outp + base);
#pragma unroll
    for (int i = 0; i < 3; i++) d2[i] = make_float2(o[i * 2], o[i * 2 + 1]);
    if (out16) {
        __nv_bfloat162* d16 = reinterpret_cast<__nv_bfloat162*>(out16 + base);
#pragma unroll
        for (int i = 0; i < 3; i++) d16[i] = __floats2bfloat162_rn(o[i * 2], o[i * 2 + 1]);
    }
}

// ---------------------------------------------------------------------------
// Host orchestration
// ---------------------------------------------------------------------------
extern "C" void kernel_launch(void* const* d_in, const int* in_sizes, int n_in,
                              void* d_out, int out_size) {
    (void)in_sizes; (void)n_in; (void)out_size;
    const float* src  = (const float*)d_in[0];
    const int*   inds = (const int*)d_in[1];
    const float* pos  = (const float*)d_in[3];
    const int*   bid  = (const int*)d_in[4];
    const float* ipw  = (const float*)d_in[5];
    const float* ipb  = (const float*)d_in[6];
    const float* opw  = (const float*)d_in[7];
    const float* opb  = (const float*)d_in[8];
    const float* l1w  = (const float*)d_in[9];
    const float* l1b  = (const float*)d_in[10];
    const float* l2w  = (const float*)d_in[11];
    const float* l2b  = (const float*)d_in[12];
    const float* n1w  = (const float*)d_in[13];
    const float* n1b  = (const float*)d_in[14];
    const float* n2w  = (const float*)d_in[15];
    const float* n2b  = (const float*)d_in[16];
    const float* n3w  = (const float*)d_in[17];
    const float* n3b  = (const float*)d_in[18];

    float* out = (float*)d_out;

    float *f32B, *f32C, *f32D, *f32E;
    __nv_bfloat16 *qin16, *feat16, *q16, *k16, *v16, *x16, *h16, *w16;
    cudaGetSymbolAddress((void**)&f32B, g_f32B);
    cudaGetSymbolAddress((void**)&f32C, g_f32C);
    cudaGetSymbolAddress((void**)&f32D, g_f32D);
    cudaGetSymbolAddress((void**)&f32E, g_f32E);
    cudaGetSymbolAddress((void**)&qin16, g_qin16);
    cudaGetSymbolAddress((void**)&feat16, g_feat16);
    cudaGetSymbolAddress((void**)&q16, g_q16);
    cudaGetSymbolAddress((void**)&k16, g_k16);
    cudaGetSymbolAddress((void**)&v16, g_v16);
    cudaGetSymbolAddress((void**)&x16, g_x16);
    cudaGetSymbolAddress((void**)&h16, g_h16);
    cudaGetSymbolAddress((void**)&w16, g_w16);

    // Pre-convert weights to bf16
    cvt_kernel<<<(221184 / 4 + 255) / 256, 256>>>(ipw, w16 + IPW_OFF, 221184 / 4);
    cvt_kernel<<<(73728 / 4 + 255) / 256, 256>>>(opw, w16 + OPW_OFF, 73728 / 4);
    cvt_kernel<<<(294912 / 4 + 255) / 256, 256>>>(l1w, w16 + L1W_OFF, 294912 / 4);
    cvt_kernel<<<(294912 / 4 + 255) / 256, 256>>>(l2w, w16 + L2W_OFF, 294912 / 4);

    const int TOT4 = NVOX * (CDIM / 4);
    dim3 gthr(256);
    dim3 ggrid((TOT4 + 255) / 256);
    dim3 grid192(CDIM / 64, NVOX / 128);
    dim3 grid768(DFF / 64, NVOX / 128);
    dim3 lngrid(NVOX / 8);

    for (int i = 0; i < 2; i++) {
        const __nv_bfloat16* Wq = w16 + IPW_OFF + (size_t)i * 3 * CDIM * CDIM;
        const __nv_bfloat16* Wk = Wq + CDIM * CDIM;
        const __nv_bfloat16* Wv = Wk + CDIM * CDIM;
        const float* bq = ipb + (size_t)i * 3 * CDIM;
        const float* bk = bq + CDIM;
        const float* bv = bk + CDIM;
        const float* posL = pos + (size_t)i * NVOX * CDIM;
        const float* cur = (i == 0) ? src : out;

        // 1. gather -> bf16 qin, feat
        gather_kernel<<<ggrid, gthr>>>(cur, posL, inds, bid, i, qin16, feat16);

        // 2. QKV projections (bf16 tensor cores)
        gemm_bf16_kernel<__nv_bfloat16, false><<<grid192, 256>>>(qin16, Wq, bq, q16, NVOX, CDIM, CDIM);
        gemm_bf16_kernel<__nv_bfloat16, false><<<grid192, 256>>>(qin16, Wk, bk, k16, NVOX, CDIM, CDIM);
        gemm_bf16_kernel<__nv_bfloat16, false><<<grid192, 256>>>(feat16, Wv, bv, v16, NVOX, CDIM, CDIM);

        // 3. attention -> qin16 (reuse)
        attn_kernel<<<NSET, 288>>>(q16, k16, v16, qin16);

        // 4. out_proj -> f32B
        gemm_bf16_kernel<float, false><<<grid192, 256>>>(
            qin16, w16 + OPW_OFF + (size_t)i * CDIM * CDIM, opb + (size_t)i * CDIM,
            f32B, NVOX, CDIM, CDIM);

        // 5. scatter + residual -> f32C
        scatter_kernel<<<ggrid, gthr>>>(cur, f32B, inds, bid, i, f32C);

        // 6. norm1 -> f32D (+ bf16 x16 for lin1)
        ln_kernel<<<lngrid, 256>>>(f32C, nullptr, n1w + i * CDIM, n1b + i * CDIM, f32D, x16);

        // 7. FFN lin1 + relu -> h16
        gemm_bf16_kernel<__nv_bfloat16, true><<<grid768, 256>>>(
            x16, w16 + L1W_OFF + (size_t)i * DFF * CDIM, l1b + (size_t)i * DFF,
            h16, NVOX, DFF, CDIM);

        // 8. FFN lin2 -> f32E
        gemm_bf16_kernel<float, false><<<grid192, 256>>>(
            h16, w16 + L2W_OFF + (size_t)i * CDIM * DFF, l2b + (size_t)i * CDIM,
            f32E, NVOX, CDIM, DFF);

        // 9. norm2: LN(x + ffn) -> f32C
        ln_kernel<<<lngrid, 256>>>(f32D, f32E, n2w + i * CDIM, n2b + i * CDIM, f32C, nullptr);

        // 10. norm3: LN(x2 + identity) -> out
        ln_kernel<<<lngrid, 256>>>(f32C, cur, n3w + i * CDIM, n3b + i * CDIM, out, nullptr);
    }
}

// round 5
// speedup vs baseline: 4.9038x; 1.0603x over previous
#include <cuda_runtime.h>
#include <cuda_bf16.h>
#include <math.h>
#include <stdint.h>

// Problem constants
#define NVOX 147456
#define CDIM 192
#define NH 8
#define DH 24
#define DFF 768
#define SETSZ 36
#define NSET 4096

// ---------------------------------------------------------------------------
// Scratch (device globals)
// ---------------------------------------------------------------------------
__device__ __nv_bfloat16 g_qk16[(size_t)NVOX * 2 * CDIM];  // fused Q|K (stride 384)
__device__ __nv_bfloat16 g_qin16[(size_t)NVOX * CDIM];     // q_in / attn out
__device__ __nv_bfloat16 g_feat16[(size_t)NVOX * CDIM];
__device__ __nv_bfloat16 g_v16[(size_t)NVOX * CDIM];
__device__ __nv_bfloat16 g_x16[(size_t)NVOX * CDIM];
__device__ __nv_bfloat16 g_h16[(size_t)NVOX * DFF];
__device__ float g_op32[(size_t)NVOX * CDIM];
__device__ float g_x32[(size_t)NVOX * CDIM];
__device__ float g_ffn32[(size_t)NVOX * CDIM];
// bf16 weights: [ipw | opw | l1w | l2w]
#define IPW_OFF 0
#define OPW_OFF 221184
#define L1W_OFF 294912
#define L2W_OFF 589824
__device__ __nv_bfloat16 g_w16[884736];

// ---------------------------------------------------------------------------
// mma.sync helpers
// ---------------------------------------------------------------------------
__device__ __forceinline__ void cp16(uint32_t dst, const void* src) {
    asm volatile("cp.async.cg.shared.global [%0], [%1], 16;\n" :: "r"(dst), "l"(src));
}
__device__ __forceinline__ void ldsm4(uint32_t* r, uint32_t addr) {
    asm volatile("ldmatrix.sync.aligned.m8n8.x4.shared.b16 {%0,%1,%2,%3}, [%4];"
                 : "=r"(r[0]), "=r"(r[1]), "=r"(r[2]), "=r"(r[3]) : "r"(addr));
}
__device__ __forceinline__ void mma_bf16(float* c, const uint32_t* a, const uint32_t* b) {
    asm volatile(
        "mma.sync.aligned.m16n8k16.row.col.f32.bf16.bf16.f32 "
        "{%0,%1,%2,%3},{%4,%5,%6,%7},{%8,%9},{%0,%1,%2,%3};"
        : "+f"(c[0]), "+f"(c[1]), "+f"(c[2]), "+f"(c[3])
        : "r"(a[0]), "r"(a[1]), "r"(a[2]), "r"(a[3]), "r"(b[0]), "r"(b[1]));
}

// ---------------------------------------------------------------------------
// bf16 GEMM: D[M,Nc] = A[M,K] @ W[Nc,K]^T + bias (opt ReLU)
// Tile 256x64x32, 8 warps (4m x 2n), warp tile 64x32, 3-stage cp.async.
// grid = (Nc/64, M/256), 256 threads, dynamic smem 60KB.
// ---------------------------------------------------------------------------
#define GA_STAGE 16384          // 256 rows x 64B
#define GB_STAGE 4096           // 64 rows x 64B
#define GB_BASE  (3 * GA_STAGE) // 49152
#define GEMM_SMEM (3 * GA_STAGE + 3 * GB_STAGE)  // 61440

template <typename OutT, bool RELU>
__global__ __launch_bounds__(256) void gemm_bf16_kernel(
        const __nv_bfloat16* __restrict__ A,
        const __nv_bfloat16* __restrict__ W,
        const float* __restrict__ bias,
        OutT* __restrict__ D,
        int K, int Nc) {
    extern __shared__ unsigned char smem[];
    const uint32_t sbase = (uint32_t)__cvta_generic_to_shared(smem);

    const int tid = threadIdx.x;
    const int lane = tid & 31;
    const int wid = tid >> 5;
    const int wm = (wid & 3) * 64;   // warp m offset (4 m-warps)
    const int wn = (wid >> 2) * 32;  // warp n offset (2 n-warps)
    const int m0 = blockIdx.y * 256;
    const int n0 = blockIdx.x * 64;

    float acc[4][4][4];
#pragma unroll
    for (int mt = 0; mt < 4; mt++)
#pragma unroll
        for (int nt = 0; nt < 4; nt++)
#pragma unroll
            for (int r = 0; r < 4; r++) acc[mt][nt][r] = 0.f;

    auto stage = [&](int kt, int buf) {
        const int k0 = kt * 32;
        const uint32_t aB = sbase + buf * GA_STAGE;
        const uint32_t bB = sbase + GB_BASE + buf * GB_STAGE;
        // A: 256 rows x 4 chunks = 1024 chunks, 4/thread
#pragma unroll
        for (int i = 0; i < 4; i++) {
            int idx = i * 256 + tid;
            int row = idx >> 2, ch = idx & 3;
            uint32_t dst = aB + row * 64 + ((ch ^ ((row >> 1) & 3)) * 16);
            cp16(dst, A + (size_t)(m0 + row) * K + k0 + ch * 8);
        }
        // B: 64 rows x 4 chunks = 256 chunks, 1/thread
        {
            int row = tid >> 2, ch = tid & 3;
            uint32_t dst = bB + row * 64 + ((ch ^ ((row >> 1) & 3)) * 16);
            cp16(dst, W + (size_t)(n0 + row) * K + k0 + ch * 8);
        }
        asm volatile("cp.async.commit_group;" ::: "memory");
    };

    const int nk = K >> 5;
    stage(0, 0);
    stage(1, 1);

    for (int t = 0; t < nk; t++) {
        const int buf = t % 3;
        asm volatile("cp.async.wait_group 1;" ::: "memory");
        __syncthreads();

        const uint32_t aB = sbase + buf * GA_STAGE;
        const uint32_t bB = sbase + GB_BASE + buf * GB_STAGE;
#pragma unroll
        for (int ks = 0; ks < 2; ks++) {
            uint32_t af[4][4], bf[4][2];
#pragma unroll
            for (int mt = 0; mt < 4; mt++) {
                int row = wm + mt * 16 + (lane & 15);
                int ch = ks * 2 + (lane >> 4);
                ldsm4(af[mt], aB + row * 64 + ((ch ^ ((row >> 1) & 3)) * 16));
            }
#pragma unroll
            for (int p = 0; p < 2; p++) {
                int row = wn + p * 16 + ((lane >> 4) << 3) + (lane & 7);
                int ch = ks * 2 + ((lane >> 3) & 1);
                uint32_t r4[4];
                ldsm4(r4, bB + row * 64 + ((ch ^ ((row >> 1) & 3)) * 16));
                bf[p * 2 + 0][0] = r4[0]; bf[p * 2 + 0][1] = r4[1];
                bf[p * 2 + 1][0] = r4[2]; bf[p * 2 + 1][1] = r4[3];
            }
#pragma unroll
            for (int mt = 0; mt < 4; mt++)
#pragma unroll
                for (int nt = 0; nt < 4; nt++)
                    mma_bf16(acc[mt][nt], af[mt], bf[nt]);
        }
        __syncthreads();
        if (t + 2 < nk) stage(t + 2, (t + 2) % 3);
    }

    // Epilogue
#pragma unroll
    for (int mt = 0; mt < 4; mt++) {
#pragma unroll
        for (int nt = 0; nt < 4; nt++) {
            int m = m0 + wm + mt * 16 + (lane >> 2);
            int n = n0 + wn + nt * 8 + (lane & 3) * 2;
            float b0 = bias[n], b1 = bias[n + 1];
            float v0 = acc[mt][nt][0] + b0;
            float v1 = acc[mt][nt][1] + b1;
            float v2 = acc[mt][nt][2] + b0;
            float v3 = acc[mt][nt][3] + b1;
            if (RELU) {
                v0 = fmaxf(v0, 0.f); v1 = fmaxf(v1, 0.f);
                v2 = fmaxf(v2, 0.f); v3 = fmaxf(v3, 0.f);
            }
            if constexpr (sizeof(OutT) == 2) {
                __nv_bfloat162* d2a = reinterpret_cast<__nv_bfloat162*>((__nv_bfloat16*)D + (size_t)m * Nc + n);
                __nv_bfloat162* d2b = reinterpret_cast<__nv_bfloat162*>((__nv_bfloat16*)D + (size_t)(m + 8) * Nc + n);
                *d2a = __floats2bfloat162_rn(v0, v1);
                *d2b = __floats2bfloat162_rn(v2, v3);
            } else {
                *reinterpret_cast<float2*>((float*)D + (size_t)m * Nc + n) = make_float2(v0, v1);
                *reinterpret_cast<float2*>((float*)D + (size_t)(m + 8) * Nc + n) = make_float2(v2, v3);
            }
        }
    }
}

// ---------------------------------------------------------------------------
// fp32 -> bf16 converter (weights)
// ---------------------------------------------------------------------------
__global__ void cvt_kernel(const float* __restrict__ src, __nv_bfloat16* __restrict__ dst, int n4) {
    int i = blockIdx.x * blockDim.x + threadIdx.x;
    if (i >= n4) return;
    float4 v = reinterpret_cast<const float4*>(src)[i];
    reinterpret_cast<__nv_bfloat162*>(dst)[i * 2 + 0] = __floats2bfloat162_rn(v.x, v.y);
    reinterpret_cast<__nv_bfloat162*>(dst)[i * 2 + 1] = __floats2bfloat162_rn(v.z, v.w);
}

// ---------------------------------------------------------------------------
// Gather: qin16[p] = bf16(cur[v] + pos[v]); feat16[p] = bf16(cur[v])
// ---------------------------------------------------------------------------
__global__ void gather_kernel(const float* __restrict__ cur,
                              const float* __restrict__ pos,
                              const int* __restrict__ inds_all,
                              const int* __restrict__ block_id,
                              int layer,
                              __nv_bfloat16* __restrict__ qin,
                              __nv_bfloat16* __restrict__ feat) {
    int gid = blockIdx.x * blockDim.x + threadIdx.x;
    const int TOT = NVOX * (CDIM / 4);
    if (gid >= TOT) return;
    int p = gid / (CDIM / 4);
    int c4 = gid % (CDIM / 4);
    int shift = block_id[0] & 1;
    const int* inds = inds_all + ((size_t)shift * 2 + layer) * NVOX;
    int v = inds[p];
    float4 f = reinterpret_cast<const float4*>(cur)[(size_t)v * (CDIM / 4) + c4];
    float4 pp = reinterpret_cast<const float4*>(pos)[(size_t)v * (CDIM / 4) + c4];
    __nv_bfloat162* f2 = reinterpret_cast<__nv_bfloat162*>(feat);
    __nv_bfloat162* q2 = reinterpret_cast<__nv_bfloat162*>(qin);
    f2[gid * 2 + 0] = __floats2bfloat162_rn(f.x, f.y);
    f2[gid * 2 + 1] = __floats2bfloat162_rn(f.z, f.w);
    q2[gid * 2 + 0] = __floats2bfloat162_rn(f.x + pp.x, f.y + pp.y);
    q2[gid * 2 + 1] = __floats2bfloat162_rn(f.z + pp.z, f.w + pp.w);
}

// ---------------------------------------------------------------------------
// Attention: one block per set, 288 threads. Q|K fused buffer (stride 384).
// ---------------------------------------------------------------------------
__global__ __launch_bounds__(288) void attn_kernel(const __nv_bfloat16* __restrict__ qk,
                                                   const __nv_bfloat16* __restrict__ v,
                                                   __nv_bfloat16* __restrict__ o) {
    __shared__ __nv_bfloat16 qks[SETSZ * 384];
    __shared__ __nv_bfloat16 vs[SETSZ * CDIM];
    int s = blockIdx.x;
    int tid = threadIdx.x;

    const uint4* qk8 = reinterpret_cast<const uint4*>(qk + (size_t)s * SETSZ * 384);
    const uint4* v8 = reinterpret_cast<const uint4*>(v + (size_t)s * SETSZ * CDIM);
    for (int idx = tid; idx < SETSZ * 384 / 8; idx += 288)
        reinterpret_cast<uint4*>(qks)[idx] = qk8[idx];
    for (int idx = tid; idx < SETSZ * CDIM / 8; idx += 288)
        reinterpret_cast<uint4*>(vs)[idx] = v8[idx];
    __syncthreads();

    int l = tid % SETSZ;
    int h = tid / SETSZ;

    float qr[DH];
#pragma unroll
    for (int d = 0; d < DH; d++) qr[d] = __bfloat162float(qks[l * 384 + h * DH + d]);

    const float scale = 0.20412414523193154f;
    float sc[SETSZ];
    float mx = -1e30f;
#pragma unroll 4
    for (int m = 0; m < SETSZ; m++) {
        const __nv_bfloat16* kr = qks + m * 384 + 192 + h * DH;
        float dot = 0.f;
#pragma unroll
        for (int d = 0; d < DH; d++) dot += qr[d] * __bfloat162float(kr[d]);
        dot *= scale;
        sc[m] = dot;
        mx = fmaxf(mx, dot);
    }
    float sum = 0.f;
#pragma unroll 4
    for (int m = 0; m < SETSZ; m++) {
        sc[m] = expf(sc[m] - mx);
        sum += sc[m];
    }
    float inv = 1.0f / sum;
    __nv_bfloat162* o2 = reinterpret_cast<__nv_bfloat162*>(o + (size_t)s * SETSZ * CDIM + l * CDIM + h * DH);
#pragma unroll
    for (int d2 = 0; d2 < DH / 2; d2++) {
        float a0 = 0.f, a1 = 0.f;
#pragma unroll 4
        for (int m = 0; m < SETSZ; m++) {
            float p = sc[m];
            a0 += p * __bfloat162float(vs[m * CDIM + h * DH + d2 * 2]);
            a1 += p * __bfloat162float(vs[m * CDIM + h * DH + d2 * 2 + 1]);
        }
        o2[d2] = __floats2bfloat162_rn(a0 * inv, a1 * inv);
    }
}

// ---------------------------------------------------------------------------
// Warp LayerNorm helper
// ---------------------------------------------------------------------------
__device__ __forceinline__ void warp_ln6(const float v[6], const float* __restrict__ w,
                                         const float* __restrict__ b, int lane, float o[6]) {
    float s = 0.f, s2 = 0.f;
#pragma unroll
    for (int i = 0; i < 6; i++) { s += v[i]; s2 += v[i] * v[i]; }
#pragma unroll
    for (int off = 16; off > 0; off >>= 1) {
        s += __shfl_xor_sync(0xffffffffu, s, off);
        s2 += __shfl_xor_sync(0xffffffffu, s2, off);
    }
    float mean = s * (1.0f / CDIM);
    float var = s2 * (1.0f / CDIM) - mean * mean;
    float r = rsqrtf(var + 1e-5f);
#pragma unroll
    for (int i = 0; i < 6; i++)
        o[i] = (v[i] - mean) * r * w[lane * 6 + i] + b[lane * 6 + i];
}

// ---------------------------------------------------------------------------
// Fused scatter + residual + LN1: warp per set-position p.
// ---------------------------------------------------------------------------
__global__ __launch_bounds__(256) void scatter_ln1_kernel(
        const float* __restrict__ cur, const float* __restrict__ oproj,
        const int* __restrict__ inds_all, const int* __restrict__ block_id, int layer,
        const float* __restrict__ w, const float* __restrict__ b,
        float* __restrict__ x32, __nv_bfloat16* __restrict__ x16) {
    int warp = threadIdx.x >> 5, lane = threadIdx.x & 31;
    int p = blockIdx.x * 8 + warp;
    int shift = block_id[0] & 1;
    int v = inds_all[((size_t)shift * 2 + layer) * NVOX + p];

    float val[6];
    const float2* o2 = reinterpret_cast<const float2*>(oproj + (size_t)p * CDIM + lane * 6);
    const float2* c2 = reinterpret_cast<const float2*>(cur + (size_t)v * CDIM + lane * 6);
#pragma unroll
    for (int i = 0; i < 3; i++) {
        float2 a = o2[i], cc = c2[i];
        val[i * 2] = a.x + cc.x; val[i * 2 + 1] = a.y + cc.y;
    }
    float o[6];
    warp_ln6(val, w, b, lane, o);
    float2* d2 = reinterpret_cast<float2*>(x32 + (size_t)v * CDIM + lane * 6);
    __nv_bfloat162* d16 = reinterpret_cast<__nv_bfloat162*>(x16 + (size_t)v * CDIM + lane * 6);
#pragma unroll
    for (int i = 0; i < 3; i++) {
        d2[i] = make_float2(o[i * 2], o[i * 2 + 1]);
        d16[i] = __floats2bfloat162_rn(o[i * 2], o[i * 2 + 1]);
    }
}

// ---------------------------------------------------------------------------
// Fused LN2 + LN3: warp per voxel row.
// ---------------------------------------------------------------------------
__global__ __launch_bounds__(256) void ln2ln3_kernel(
        const float* __restrict__ x, const float* __restrict__ ffn,
        const float* __restrict__ idn,
        const float* __restrict__ w2, const float* __restrict__ b2,
        const float* __restrict__ w3, const float* __restrict__ b3,
        float* __restrict__ outp) {
    int warp = threadIdx.x >> 5, lane = threadIdx.x & 31;
    int row = blockIdx.x * 8 + warp;
    size_t base = (size_t)row * CDIM + lane * 6;

    float t[6];
    const float2* x2p = reinterpret_cast<const float2*>(x + base);
    const float2* f2p = reinterpret_cast<const float2*>(ffn + base);
#pragma unroll
    for (int i = 0; i < 3; i++) {
        float2 a = x2p[i], ff = f2p[i];
        t[i * 2] = a.x + ff.x; t[i * 2 + 1] = a.y + ff.y;
    }
    float x2[6];
    warp_ln6(t, w2, b2, lane, x2);

    const float2* i2p = reinterpret_cast<const float2*>(idn + base);
#pragma unroll
    for (int i = 0; i < 3; i++) {
        float2 a = i2p[i];
        x2[i * 2] += a.x; x2[i * 2 + 1] += a.y;
    }
    float o[6];
    warp_ln6(x2, w3, b3, lane, o);
    float2* d2 = reinterpret_cast<float2*>(outp + base);
#pragma unroll
    for (int i = 0; i < 3; i++) d2[i] = make_float2(o[i * 2], o[i * 2 + 1]);
}

// ---------------------------------------------------------------------------
// Host orchestration
// ---------------------------------------------------------------------------
extern "C" void kernel_launch(void* const* d_in, const int* in_sizes, int n_in,
                              void* d_out, int out_size) {
    (void)in_sizes; (void)n_in; (void)out_size;
    const float* src  = (const float*)d_in[0];
    const int*   inds = (const int*)d_in[1];
    const float* pos  = (const float*)d_in[3];
    const int*   bid  = (const int*)d_in[4];
    const float* ipw  = (const float*)d_in[5];
    const float* ipb  = (const float*)d_in[6];
    const float* opw  = (const float*)d_in[7];
    const float* opb  = (const float*)d_in[8];
    const float* l1w  = (const float*)d_in[9];
    const float* l1b  = (const float*)d_in[10];
    const float* l2w  = (const float*)d_in[11];
    const float* l2b  = (const float*)d_in[12];
    const float* n1w  = (const float*)d_in[13];
    const float* n1b  = (const float*)d_in[14];
    const float* n2w  = (const float*)d_in[15];
    const float* n2b  = (const float*)d_in[16];
    const float* n3w  = (const float*)d_in[17];
    const float* n3b  = (const float*)d_in[18];

    float* out = (float*)d_out;

    __nv_bfloat16 *qk16, *qin16, *feat16, *v16, *x16, *h16, *w16;
    float *op32, *x32, *ffn32;
    cudaGetSymbolAddress((void**)&qk16, g_qk16);
    cudaGetSymbolAddress((void**)&qin16, g_qin16);
    cudaGetSymbolAddress((void**)&feat16, g_feat16);
    cudaGetSymbolAddress((void**)&v16, g_v16);
    cudaGetSymbolAddress((void**)&x16, g_x16);
    cudaGetSymbolAddress((void**)&h16, g_h16);
    cudaGetSymbolAddress((void**)&w16, g_w16);
    cudaGetSymbolAddress((void**)&op32, g_op32);
    cudaGetSymbolAddress((void**)&x32, g_x32);
    cudaGetSymbolAddress((void**)&ffn32, g_ffn32);

    cudaFuncSetAttribute((const void*)gemm_bf16_kernel<__nv_bfloat16, false>,
                         cudaFuncAttributeMaxDynamicSharedMemorySize, GEMM_SMEM);
    cudaFuncSetAttribute((const void*)gemm_bf16_kernel<__nv_bfloat16, true>,
                         cudaFuncAttributeMaxDynamicSharedMemorySize, GEMM_SMEM);
    cudaFuncSetAttribute((const void*)gemm_bf16_kernel<float, false>,
                         cudaFuncAttributeMaxDynamicSharedMemorySize, GEMM_SMEM);

    // Pre-convert weights to bf16
    cvt_kernel<<<(221184 / 4 + 255) / 256, 256>>>(ipw, w16 + IPW_OFF, 221184 / 4);
    cvt_kernel<<<(73728 / 4 + 255) / 256, 256>>>(opw, w16 + OPW_OFF, 73728 / 4);
    cvt_kernel<<<(294912 / 4 + 255) / 256, 256>>>(l1w, w16 + L1W_OFF, 294912 / 4);
    cvt_kernel<<<(294912 / 4 + 255) / 256, 256>>>(l2w, w16 + L2W_OFF, 294912 / 4);

    const int TOT4 = NVOX * (CDIM / 4);
    dim3 ggrid((TOT4 + 255) / 256);
    dim3 gridQK(2 * CDIM / 64, NVOX / 256);   // (6, 576)
    dim3 grid192(CDIM / 64, NVOX / 256);      // (3, 576)
    dim3 grid768(DFF / 64, NVOX / 256);       // (12, 576)
    dim3 rowgrid(NVOX / 8);

    for (int i = 0; i < 2; i++) {
        const __nv_bfloat16* Wqk = w16 + IPW_OFF + (size_t)i * 3 * CDIM * CDIM;  // Wq|Wk
        const __nv_bfloat16* Wv = Wqk + 2 * CDIM * CDIM;
        const float* bqk = ipb + (size_t)i * 3 * CDIM;
        const float* bv = bqk + 2 * CDIM;
        const float* posL = pos + (size_t)i * NVOX * CDIM;
        const float* cur = (i == 0) ? src : out;

        // 1. gather -> bf16 qin, feat
        gather_kernel<<<ggrid, 256>>>(cur, posL, inds, bid, i, qin16, feat16);

        // 2. QK fused projection (Nc=384) and V projection
        gemm_bf16_kernel<__nv_bfloat16, false><<<gridQK, 256, GEMM_SMEM>>>(
            qin16, Wqk, bqk, qk16, CDIM, 2 * CDIM);
        gemm_bf16_kernel<__nv_bfloat16, false><<<grid192, 256, GEMM_SMEM>>>(
            feat16, Wv, bv, v16, CDIM, CDIM);

        // 3. attention -> qin16
        attn_kernel<<<NSET, 288>>>(qk16, v16, qin16);

        // 4. out_proj -> op32 (fp32)
        gemm_bf16_kernel<float, false><<<grid192, 256, GEMM_SMEM>>>(
            qin16, w16 + OPW_OFF + (size_t)i * CDIM * CDIM, opb + (size_t)i * CDIM,
            op32, CDIM, CDIM);

        // 5. fused scatter + residual + LN1 -> x32 (fp32), x16 (bf16)
        scatter_ln1_kernel<<<rowgrid, 256>>>(cur, op32, inds, bid, i,
                                             n1w + i * CDIM, n1b + i * CDIM, x32, x16);

        // 6. FFN lin1 + relu -> h16
        gemm_bf16_kernel<__nv_bfloat16, true><<<grid768, 256, GEMM_SMEM>>>(
            x16, w16 + L1W_OFF + (size_t)i * DFF * CDIM, l1b + (size_t)i * DFF,
            h16, CDIM, DFF);

        // 7. FFN lin2 -> ffn32 (fp32)
        gemm_bf16_kernel<float, false><<<grid192, 256, GEMM_SMEM>>>(
            h16, w16 + L2W_OFF + (size_t)i * CDIM * DFF, l2b + (size_t)i * CDIM,
            ffn32, DFF, CDIM);

        // 8. fused LN2 + LN3 -> out
        ln2ln3_kernel<<<rowgrid, 256>>>(x32, ffn32, cur,
                                        n2w + i * CDIM, n2b + i * CDIM,
                                        n3w + i * CDIM, n3b + i * CDIM, out);
    }
}

// round 8
// speedup vs baseline: 4.9369x; 1.0067x over previous
#include <cuda_runtime.h>
#include <cuda_bf16.h>
#include <math.h>
#include <stdint.h>

// Problem constants
#define NVOX 147456
#define CDIM 192
#define NH 8
#define DH 24
#define DFF 768
#define SETSZ 36
#define NSET 4096

// ---------------------------------------------------------------------------
// Scratch (device globals)
// ---------------------------------------------------------------------------
__device__ __nv_bfloat16 g_qk16[(size_t)NVOX * 2 * CDIM];  // fused Q|K (stride 384)
__device__ __nv_bfloat16 g_qin16[(size_t)NVOX * CDIM];     // q_in / attn out
__device__ __nv_bfloat16 g_feat16[(size_t)NVOX * CDIM];
__device__ __nv_bfloat16 g_v16[(size_t)NVOX * CDIM];
__device__ __nv_bfloat16 g_x16[(size_t)NVOX * CDIM];
__device__ __nv_bfloat16 g_h16[(size_t)NVOX * DFF];
__device__ float g_x32[(size_t)NVOX * CDIM];   // post-LN1 x (fp32)
// bf16 weights: [ipw | opw | l1w | l2w]
#define IPW_OFF 0
#define OPW_OFF 221184
#define L1W_OFF 294912
#define L2W_OFF 589824
__device__ __nv_bfloat16 g_w16[884736];

// ---------------------------------------------------------------------------
// mma.sync helpers
// ---------------------------------------------------------------------------
__device__ __forceinline__ void cp16(uint32_t dst, const void* src) {
    asm volatile("cp.async.cg.shared.global [%0], [%1], 16;\n" :: "r"(dst), "l"(src));
}
__device__ __forceinline__ void ldsm4(uint32_t* r, uint32_t addr) {
    asm volatile("ldmatrix.sync.aligned.m8n8.x4.shared.b16 {%0,%1,%2,%3}, [%4];"
                 : "=r"(r[0]), "=r"(r[1]), "=r"(r[2]), "=r"(r[3]) : "r"(addr));
}
__device__ __forceinline__ void mma_bf16(float* c, const uint32_t* a, const uint32_t* b) {
    asm volatile(
        "mma.sync.aligned.m16n8k16.row.col.f32.bf16.bf16.f32 "
        "{%0,%1,%2,%3},{%4,%5,%6,%7},{%8,%9},{%0,%1,%2,%3};"
        : "+f"(c[0]), "+f"(c[1]), "+f"(c[2]), "+f"(c[3])
        : "r"(a[0]), "r"(a[1]), "r"(a[2]), "r"(a[3]), "r"(b[0]), "r"(b[1]));
}
// Drain helper: last chunk must wait for ITS OWN group (wait_group 0);
// earlier chunks may leave the next prefetch in flight (wait_group 1).
__device__ __forceinline__ void cp_wait(bool last) {
    if (last) asm volatile("cp.async.wait_group 0;" ::: "memory");
    else      asm volatile("cp.async.wait_group 1;" ::: "memory");
}

// ---------------------------------------------------------------------------
// Plain bf16 GEMM (QK / V / lin1): tile 256x64x32, 8 warps (4m x 2n), 3-stage.
// ---------------------------------------------------------------------------
#define GA_STAGE 16384
#define GB_STAGE 4096
#define GB_BASE  (3 * GA_STAGE)
#define GEMM_SMEM (3 * GA_STAGE + 3 * GB_STAGE)  // 61440

template <typename OutT, bool RELU>
__global__ __launch_bounds__(256) void gemm_bf16_kernel(
        const __nv_bfloat16* __restrict__ A,
        const __nv_bfloat16* __restrict__ W,
        const float* __restrict__ bias,
        OutT* __restrict__ D,
        int K, int Nc) {
    extern __shared__ unsigned char smem[];
    const uint32_t sbase = (uint32_t)__cvta_generic_to_shared(smem);

    const int tid = threadIdx.x;
    const int lane = tid & 31;
    const int wid = tid >> 5;
    const int wm = (wid & 3) * 64;
    const int wn = (wid >> 2) * 32;
    const int m0 = blockIdx.y * 256;
    const int n0 = blockIdx.x * 64;

    float acc[4][4][4];
#pragma unroll
    for (int mt = 0; mt < 4; mt++)
#pragma unroll
        for (int nt = 0; nt < 4; nt++)
#pragma unroll
            for (int r = 0; r < 4; r++) acc[mt][nt][r] = 0.f;

    auto stage = [&](int kt, int buf) {
        const int k0 = kt * 32;
        const uint32_t aB = sbase + buf * GA_STAGE;
        const uint32_t bB = sbase + GB_BASE + buf * GB_STAGE;
#pragma unroll
        for (int i = 0; i < 4; i++) {
            int idx = i * 256 + tid;
            int row = idx >> 2, ch = idx & 3;
            cp16(aB + row * 64 + ((ch ^ ((row >> 1) & 3)) * 16),
                 A + (size_t)(m0 + row) * K + k0 + ch * 8);
        }
        {
            int row = tid >> 2, ch = tid & 3;
            cp16(bB + row * 64 + ((ch ^ ((row >> 1) & 3)) * 16),
                 W + (size_t)(n0 + row) * K + k0 + ch * 8);
        }
        asm volatile("cp.async.commit_group;" ::: "memory");
    };

    const int nk = K >> 5;
    stage(0, 0);
    stage(1, 1);

    for (int t = 0; t < nk; t++) {
        const int buf = t % 3;
        cp_wait(t == nk - 1);
        __syncthreads();

        const uint32_t aB = sbase + buf * GA_STAGE;
        const uint32_t bB = sbase + GB_BASE + buf * GB_STAGE;
#pragma unroll
        for (int ks = 0; ks < 2; ks++) {
            uint32_t af[4][4], bf[4][2];
#pragma unroll
            for (int mt = 0; mt < 4; mt++) {
                int row = wm + mt * 16 + (lane & 15);
                int ch = ks * 2 + (lane >> 4);
                ldsm4(af[mt], aB + row * 64 + ((ch ^ ((row >> 1) & 3)) * 16));
            }
#pragma unroll
            for (int p = 0; p < 2; p++) {
                int row = wn + p * 16 + ((lane >> 4) << 3) + (lane & 7);
                int ch = ks * 2 + ((lane >> 3) & 1);
                uint32_t r4[4];
                ldsm4(r4, bB + row * 64 + ((ch ^ ((row >> 1) & 3)) * 16));
                bf[p * 2 + 0][0] = r4[0]; bf[p * 2 + 0][1] = r4[1];
                bf[p * 2 + 1][0] = r4[2]; bf[p * 2 + 1][1] = r4[3];
            }
#pragma unroll
            for (int mt = 0; mt < 4; mt++)
#pragma unroll
                for (int nt = 0; nt < 4; nt++)
                    mma_bf16(acc[mt][nt], af[mt], bf[nt]);
        }
        __syncthreads();
        if (t + 2 < nk) stage(t + 2, (t + 2) % 3);
    }

#pragma unroll
    for (int mt = 0; mt < 4; mt++) {
#pragma unroll
        for (int nt = 0; nt < 4; nt++) {
            int m = m0 + wm + mt * 16 + (lane >> 2);
            int n = n0 + wn + nt * 8 + (lane & 3) * 2;
            float b0 = bias[n], b1 = bias[n + 1];
            float v0 = acc[mt][nt][0] + b0;
            float v1 = acc[mt][nt][1] + b1;
            float v2 = acc[mt][nt][2] + b0;
            float v3 = acc[mt][nt][3] + b1;
            if (RELU) {
                v0 = fmaxf(v0, 0.f); v1 = fmaxf(v1, 0.f);
                v2 = fmaxf(v2, 0.f); v3 = fmaxf(v3, 0.f);
            }
            if constexpr (sizeof(OutT) == 2) {
                *reinterpret_cast<__nv_bfloat162*>((__nv_bfloat16*)D + (size_t)m * Nc + n) =
                    __floats2bfloat162_rn(v0, v1);
                *reinterpret_cast<__nv_bfloat162*>((__nv_bfloat16*)D + (size_t)(m + 8) * Nc + n) =
                    __floats2bfloat162_rn(v2, v3);
            } else {
                *reinterpret_cast<float2*>((float*)D + (size_t)m * Nc + n) = make_float2(v0, v1);
                *reinterpret_cast<float2*>((float*)D + (size_t)(m + 8) * Nc + n) = make_float2(v2, v3);
            }
        }
    }
}

// ---------------------------------------------------------------------------
// Fused GEMM mainloop config (tile 64 x 192, K chunks of 32, 3-stage).
// 8 warps = 2m x 4n; warp tile 32 x 48; acc[2][6][4] = 48 regs/thread.
// ---------------------------------------------------------------------------
#define FA_STAGE 4096           // 64 rows x 64B
#define FB_STAGE 12288          // 192 rows x 64B
#define FB_BASE  (3 * FA_STAGE)
#define FUSED_SMEM (3 * FA_STAGE + 3 * FB_STAGE)  // 49152

#define FUSED_MAINLOOP(Aptr, Wptr, Kval)                                              \
    float acc[2][6][4];                                                               \
    _Pragma("unroll")                                                                 \
    for (int mt = 0; mt < 2; mt++)                                                    \
        _Pragma("unroll")                                                             \
        for (int nt = 0; nt < 6; nt++)                                                \
            _Pragma("unroll")                                                         \
            for (int r = 0; r < 4; r++) acc[mt][nt][r] = 0.f;                         \
    auto stage = [&](int kt, int buf) {                                               \
        const int k0 = kt * 32;                                                       \
        {                                                                             \
            int row = tid >> 2, ch = tid & 3;                                         \
            cp16(sbase + buf * FA_STAGE + row * 64 + ((ch ^ ((row >> 1) & 3)) * 16),  \
                 (Aptr) + (size_t)(m0 + row) * (Kval) + k0 + ch * 8);                 \
        }                                                                             \
        _Pragma("unroll")                                                             \
        for (int i = 0; i < 3; i++) {                                                 \
            int idx = i * 256 + tid;                                                  \
            int row = idx >> 2, ch = idx & 3;                                         \
            cp16(sbase + FB_BASE + buf * FB_STAGE + row * 64 +                        \
                     ((ch ^ ((row >> 1) & 3)) * 16),                                  \
                 (Wptr) + (size_t)row * (Kval) + k0 + ch * 8);                        \
        }                                                                             \
        asm volatile("cp.async.commit_group;" ::: "memory");                          \
    };                                                                                \
    const int nk = (Kval) >> 5;                                                       \
    stage(0, 0);                                                                      \
    stage(1, 1);                                                                      \
    for (int t = 0; t < nk; t++) {                                                    \
        const int buf = t % 3;                                                        \
        cp_wait(t == nk - 1);                                                         \
        __syncthreads();                                                              \
        const uint32_t aB = sbase + buf * FA_STAGE;                                   \
        const uint32_t bB = sbase + FB_BASE + buf * FB_STAGE;                         \
        _Pragma("unroll")                                                             \
        for (int ks = 0; ks < 2; ks++) {                                              \
            uint32_t af[2][4], bf[6][2];                                              \
            _Pragma("unroll")                                                         \
            for (int mt = 0; mt < 2; mt++) {                                          \
                int row = wm + mt * 16 + (lane & 15);                                 \
                int ch = ks * 2 + (lane >> 4);                                        \
                ldsm4(af[mt], aB + row * 64 + ((ch ^ ((row >> 1) & 3)) * 16));        \
            }                                                                         \
            _Pragma("unroll")                                                         \
            for (int p = 0; p < 3; p++) {                                             \
                int row = wn + p * 16 + ((lane >> 4) << 3) + (lane & 7);              \
                int ch = ks * 2 + ((lane >> 3) & 1);                                  \
                uint32_t r4[4];                                                       \
                ldsm4(r4, bB + row * 64 + ((ch ^ ((row >> 1) & 3)) * 16));            \
                bf[p * 2 + 0][0] = r4[0]; bf[p * 2 + 0][1] = r4[1];                   \
                bf[p * 2 + 1][0] = r4[2]; bf[p * 2 + 1][1] = r4[3];                   \
            }                                                                         \
            _Pragma("unroll")                                                         \
            for (int mt = 0; mt < 2; mt++)                                            \
                _Pragma("unroll")                                                     \
                for (int nt = 0; nt < 6; nt++)                                        \
                    mma_bf16(acc[mt][nt], af[mt], bf[nt]);                            \
        }                                                                             \
        __syncthreads();                                                              \
        if (t + 2 < nk) stage(t + 2, (t + 2) % 3);                                    \
    }

// ---------------------------------------------------------------------------
// Fused out_proj + scatter + residual + LN1.
//   row p (set-order), v = inds[p]:
//   x[v] = LN1(cur[v] + (attnout[p] @ W^T + bias))  -> x32 (fp32), x16 (bf16)
// grid = NVOX/64, 256 threads.
// ---------------------------------------------------------------------------
__global__ __launch_bounds__(256) void gemm_op_ln1_kernel(
        const __nv_bfloat16* __restrict__ A,
        const __nv_bfloat16* __restrict__ W,
        const float* __restrict__ bias,
        const float* __restrict__ cur,
        const int* __restrict__ inds_all, const int* __restrict__ block_id, int layer,
        const float* __restrict__ lnw, const float* __restrict__ lnb,
        float* __restrict__ x32, __nv_bfloat16* __restrict__ x16) {
    extern __shared__ unsigned char smem[];
    const uint32_t sbase = (uint32_t)__cvta_generic_to_shared(smem);
    const int tid = threadIdx.x;
    const int lane = tid & 31;
    const int wid = tid >> 5;
    const int wm = (wid & 1) * 32;
    const int wn = (wid >> 1) * 48;
    const int m0 = blockIdx.x * 64;

    FUSED_MAINLOOP(A, W, CDIM)

    // Epilogue
    float* stats = reinterpret_cast<float*>(smem);
    const int gid = lane >> 2, tig = lane & 3;
    const int shift = block_id[0] & 1;
    const int* ip = inds_all + ((size_t)shift * 2 + layer) * NVOX;
    int vrow[2][2];
#pragma unroll
    for (int mt = 0; mt < 2; mt++) {
#pragma unroll
        for (int mm = 0; mm < 2; mm++) {
            int rloc = wm + mt * 16 + mm * 8 + gid;
            int v = ip[m0 + rloc];
            vrow[mt][mm] = v;
            float s = 0.f, s2 = 0.f;
#pragma unroll
            for (int nt = 0; nt < 6; nt++) {
                int n = wn + nt * 8 + tig * 2;
                float2 c = *reinterpret_cast<const float2*>(cur + (size_t)v * CDIM + n);
                float a0 = acc[mt][nt][mm * 2]     + bias[n]     + c.x;
                float a1 = acc[mt][nt][mm * 2 + 1] + bias[n + 1] + c.y;
                acc[mt][nt][mm * 2] = a0; acc[mt][nt][mm * 2 + 1] = a1;
                s += a0 + a1; s2 += a0 * a0 + a1 * a1;
            }
            s  += __shfl_xor_sync(0xffffffffu, s, 1);  s  += __shfl_xor_sync(0xffffffffu, s, 2);
            s2 += __shfl_xor_sync(0xffffffffu, s2, 1); s2 += __shfl_xor_sync(0xffffffffu, s2, 2);
            if (tig == 0) {
                stats[((wid >> 1) * 64 + rloc) * 2]     = s;
                stats[((wid >> 1) * 64 + rloc) * 2 + 1] = s2;
            }
        }
    }
    __syncthreads();
#pragma unroll
    for (int mt = 0; mt < 2; mt++) {
#pragma unroll
        for (int mm = 0; mm < 2; mm++) {
            int rloc = wm + mt * 16 + mm * 8 + gid;
            int v = vrow[mt][mm];
            float S = 0.f, S2 = 0.f;
#pragma unroll
            for (int g = 0; g < 4; g++) {
                S  += stats[(g * 64 + rloc) * 2];
                S2 += stats[(g * 64 + rloc) * 2 + 1];
            }
            float mean = S * (1.0f / CDIM);
            float var = S2 * (1.0f / CDIM) - mean * mean;
            float rs = rsqrtf(var + 1e-5f);
#pragma unroll
            for (int nt = 0; nt < 6; nt++) {
                int n = wn + nt * 8 + tig * 2;
                float o0 = (acc[mt][nt][mm * 2]     - mean) * rs * lnw[n]     + lnb[n];
                float o1 = (acc[mt][nt][mm * 2 + 1] - mean) * rs * lnw[n + 1] + lnb[n + 1];
                *reinterpret_cast<float2*>(x32 + (size_t)v * CDIM + n) = make_float2(o0, o1);
                *reinterpret_cast<__nv_bfloat162*>(x16 + (size_t)v * CDIM + n) =
                    __floats2bfloat162_rn(o0, o1);
            }
        }
    }
}

// ---------------------------------------------------------------------------
// Fused lin2 + LN2 + LN3 (rows are voxel-order):
//   x2 = LN2(x32[v] + (h[v] @ W^T + bias)); out[v] = LN3(x2 + cur[v])
// ---------------------------------------------------------------------------
__global__ __launch_bounds__(256) void gemm_ffn_ln23_kernel(
        const __nv_bfloat16* __restrict__ A,
        const __nv_bfloat16* __restrict__ W,
        const float* __restrict__ bias,
        const float* __restrict__ x32,
        const float* __restrict__ cur,
        const float* __restrict__ w2, const float* __restrict__ b2,
        const float* __restrict__ w3, const float* __restrict__ b3,
        float* __restrict__ outp) {
    extern __shared__ unsigned char smem[];
    const uint32_t sbase = (uint32_t)__cvta_generic_to_shared(smem);
    const int tid = threadIdx.x;
    const int lane = tid & 31;
    const int wid = tid >> 5;
    const int wm = (wid & 1) * 32;
    const int wn = (wid >> 1) * 48;
    const int m0 = blockIdx.x * 64;

    FUSED_MAINLOOP(A, W, DFF)

    float* stats = reinterpret_cast<float*>(smem);
    const int gid = lane >> 2, tig = lane & 3;

    // Pass 1: val = acc + bias + x32 ; stats for LN2
#pragma unroll
    for (int mt = 0; mt < 2; mt++) {
#pragma unroll
        for (int mm = 0; mm < 2; mm++) {
            int rloc = wm + mt * 16 + mm * 8 + gid;
            int v = m0 + rloc;
            float s = 0.f, s2 = 0.f;
#pragma unroll
            for (int nt = 0; nt < 6; nt++) {
                int n = wn + nt * 8 + tig * 2;
                float2 xr = *reinterpret_cast<const float2*>(x32 + (size_t)v * CDIM + n);
                float a0 = acc[mt][nt][mm * 2]     + bias[n]     + xr.x;
                float a1 = acc[mt][nt][mm * 2 + 1] + bias[n + 1] + xr.y;
                acc[mt][nt][mm * 2] = a0; acc[mt][nt][mm * 2 + 1] = a1;
                s += a0 + a1; s2 += a0 * a0 + a1 * a1;
            }
            s  += __shfl_xor_sync(0xffffffffu, s, 1);  s  += __shfl_xor_sync(0xffffffffu, s, 2);
            s2 += __shfl_xor_sync(0xffffffffu, s2, 1); s2 += __shfl_xor_sync(0xffffffffu, s2, 2);
            if (tig == 0) {
                stats[((wid >> 1) * 64 + rloc) * 2]     = s;
                stats[((wid >> 1) * 64 + rloc) * 2 + 1] = s2;
            }
        }
    }
    __syncthreads();

    // LN2 apply + identity residual; collect LN3 stats locally
    float sB[2][2], s2B[2][2];
#pragma unroll
    for (int mt = 0; mt < 2; mt++) {
#pragma unroll
        for (int mm = 0; mm < 2; mm++) {
            int rloc = wm + mt * 16 + mm * 8 + gid;
            int v = m0 + rloc;
            float S = 0.f, S2 = 0.f;
#pragma unroll
            for (int g = 0; g < 4; g++) {
                S  += stats[(g * 64 + rloc) * 2];
                S2 += stats[(g * 64 + rloc) * 2 + 1];
            }
            float mean = S * (1.0f / CDIM);
            float var = S2 * (1.0f / CDIM) - mean * mean;
            float rs = rsqrtf(var + 1e-5f);
            float s = 0.f, s2 = 0.f;
#pragma unroll
            for (int nt = 0; nt < 6; nt++) {
                int n = wn + nt * 8 + tig * 2;
                float2 cv = *reinterpret_cast<const float2*>(cur + (size_t)v * CDIM + n);
                float t0 = (acc[mt][nt][mm * 2]     - mean) * rs * w2[n]     + b2[n]     + cv.x;
                float t1 = (acc[mt][nt][mm * 2 + 1] - mean) * rs * w2[n + 1] + b2[n + 1] + cv.y;
                acc[mt][nt][mm * 2] = t0; acc[mt][nt][mm * 2 + 1] = t1;
                s += t0 + t1; s2 += t0 * t0 + t1 * t1;
            }
            s  += __shfl_xor_sync(0xffffffffu, s, 1);  s  += __shfl_xor_sync(0xffffffffu, s, 2);
            s2 += __shfl_xor_sync(0xffffffffu, s2, 1); s2 += __shfl_xor_sync(0xffffffffu, s2, 2);
            sB[mt][mm] = s; s2B[mt][mm] = s2;
        }
    }
    __syncthreads();  // pass-1 stat reads complete before overwrite
#pragma unroll
    for (int mt = 0; mt < 2; mt++)
#pragma unroll
        for (int mm = 0; mm < 2; mm++) {
            int rloc = wm + mt * 16 + mm * 8 + gid;
            if (tig == 0) {
                stats[((wid >> 1) * 64 + rloc) * 2]     = sB[mt][mm];
                stats[((wid >> 1) * 64 + rloc) * 2 + 1] = s2B[mt][mm];
            }
        }
    __syncthreads();

    // LN3 apply + store
#pragma unroll
    for (int mt = 0; mt < 2; mt++) {
#pragma unroll
        for (int mm = 0; mm < 2; mm++) {
            int rloc = wm + mt * 16 + mm * 8 + gid;
            int v = m0 + rloc;
            float S = 0.f, S2 = 0.f;
#pragma unroll
            for (int g = 0; g < 4; g++) {
                S  += stats[(g * 64 + rloc) * 2];
                S2 += stats[(g * 64 + rloc) * 2 + 1];
            }
            float mean = S * (1.0f / CDIM);
            float var = S2 * (1.0f / CDIM) - mean * mean;
            float rs = rsqrtf(var + 1e-5f);
#pragma unroll
            for (int nt = 0; nt < 6; nt++) {
                int n = wn + nt * 8 + tig * 2;
                float o0 = (acc[mt][nt][mm * 2]     - mean) * rs * w3[n]     + b3[n];
                float o1 = (acc[mt][nt][mm * 2 + 1] - mean) * rs * w3[n + 1] + b3[n + 1];
                *reinterpret_cast<float2*>(outp + (size_t)v * CDIM + n) = make_float2(o0, o1);
            }
        }
    }
}

// ---------------------------------------------------------------------------
// fp32 -> bf16 converter (weights)
// ---------------------------------------------------------------------------
__global__ void cvt_kernel(const float* __restrict__ src, __nv_bfloat16* __restrict__ dst, int n4) {
    int i = blockIdx.x * blockDim.x + threadIdx.x;
    if (i >= n4) return;
    float4 v = reinterpret_cast<const float4*>(src)[i];
    reinterpret_cast<__nv_bfloat162*>(dst)[i * 2 + 0] = __floats2bfloat162_rn(v.x, v.y);
    reinterpret_cast<__nv_bfloat162*>(dst)[i * 2 + 1] = __floats2bfloat162_rn(v.z, v.w);
}

// ---------------------------------------------------------------------------
// Gather
// ---------------------------------------------------------------------------
__global__ void gather_kernel(const float* __restrict__ cur,
                              const float* __restrict__ pos,
                              const int* __restrict__ inds_all,
                              const int* __restrict__ block_id,
                              int layer,
                              __nv_bfloat16* __restrict__ qin,
                              __nv_bfloat16* __restrict__ feat) {
    int gid = blockIdx.x * blockDim.x + threadIdx.x;
    const int TOT = NVOX * (CDIM / 4);
    if (gid >= TOT) return;
    int p = gid / (CDIM / 4);
    int c4 = gid % (CDIM / 4);
    int shift = block_id[0] & 1;
    const int* inds = inds_all + ((size_t)shift * 2 + layer) * NVOX;
    int v = inds[p];
    float4 f = reinterpret_cast<const float4*>(cur)[(size_t)v * (CDIM / 4) + c4];
    float4 pp = reinterpret_cast<const float4*>(pos)[(size_t)v * (CDIM / 4) + c4];
    __nv_bfloat162* f2 = reinterpret_cast<__nv_bfloat162*>(feat);
    __nv_bfloat162* q2 = reinterpret_cast<__nv_bfloat162*>(qin);
    f2[gid * 2 + 0] = __floats2bfloat162_rn(f.x, f.y);
    f2[gid * 2 + 1] = __floats2bfloat162_rn(f.z, f.w);
    q2[gid * 2 + 0] = __floats2bfloat162_rn(f.x + pp.x, f.y + pp.y);
    q2[gid * 2 + 1] = __floats2bfloat162_rn(f.z + pp.z, f.w + pp.w);
}

// ---------------------------------------------------------------------------
// Attention: one block per set, 288 threads. Q|K fused (stride 384).
// ---------------------------------------------------------------------------
__global__ __launch_bounds__(288) void attn_kernel(const __nv_bfloat16* __restrict__ qk,
                                                   const __nv_bfloat16* __restrict__ v,
                                                   __nv_bfloat16* __restrict__ o) {
    __shared__ __nv_bfloat16 qks[SETSZ * 384];
    __shared__ __nv_bfloat16 vs[SETSZ * CDIM];
    int s = blockIdx.x;
    int tid = threadIdx.x;

    const uint4* qk8 = reinterpret_cast<const uint4*>(qk + (size_t)s * SETSZ * 384);
    const uint4* v8 = reinterpret_cast<const uint4*>(v + (size_t)s * SETSZ * CDIM);
    for (int idx = tid; idx < SETSZ * 384 / 8; idx += 288)
        reinterpret_cast<uint4*>(qks)[idx] = qk8[idx];
    for (int idx = tid; idx < SETSZ * CDIM / 8; idx += 288)
        reinterpret_cast<uint4*>(vs)[idx] = v8[idx];
    __syncthreads();

    int l = tid % SETSZ;
    int h = tid / SETSZ;

    float qr[DH];
#pragma unroll
    for (int d = 0; d < DH; d++) qr[d] = __bfloat162float(qks[l * 384 + h * DH + d]);

    const float scale = 0.20412414523193154f;
    float sc[SETSZ];
    float mx = -1e30f;
#pragma unroll 4
    for (int m = 0; m < SETSZ; m++) {
        const __nv_bfloat16* kr = qks + m * 384 + 192 + h * DH;
        float dot = 0.f;
#pragma unroll
        for (int d = 0; d < DH; d++) dot += qr[d] * __bfloat162float(kr[d]);
        dot *= scale;
        sc[m] = dot;
        mx = fmaxf(mx, dot);
    }
    float sum = 0.f;
#pragma unroll 4
    for (int m = 0; m < SETSZ; m++) {
        sc[m] = expf(sc[m] - mx);
        sum += sc[m];
    }
    float inv = 1.0f / sum;
    __nv_bfloat162* o2 = reinterpret_cast<__nv_bfloat162*>(o + (size_t)s * SETSZ * CDIM + l * CDIM + h * DH);
#pragma unroll
    for (int d2 = 0; d2 < DH / 2; d2++) {
        float a0 = 0.f, a1 = 0.f;
#pragma unroll 4
        for (int m = 0; m < SETSZ; m++) {
            float p = sc[m];
            a0 += p * __bfloat162float(vs[m * CDIM + h * DH + d2 * 2]);
            a1 += p * __bfloat162float(vs[m * CDIM + h * DH + d2 * 2 + 1]);
        }
        o2[d2] = __floats2bfloat162_rn(a0 * inv, a1 * inv);
    }
}

// ---------------------------------------------------------------------------
// Host orchestration
// ---------------------------------------------------------------------------
extern "C" void kernel_launch(void* const* d_in, const int* in_sizes, int n_in,
                              void* d_out, int out_size) {
    (void)in_sizes; (void)n_in; (void)out_size;
    const float* src  = (const float*)d_in[0];
    const int*   inds = (const int*)d_in[1];
    const float* pos  = (const float*)d_in[3];
    const int*   bid  = (const int*)d_in[4];
    const float* ipw  = (const float*)d_in[5];
    const float* ipb  = (const float*)d_in[6];
    const float* opw  = (const float*)d_in[7];
    const float* opb  = (const float*)d_in[8];
    const float* l1w  = (const float*)d_in[9];
    const float* l1b  = (const float*)d_in[10];
    const float* l2w  = (const float*)d_in[11];
    const float* l2b  = (const float*)d_in[12];
    const float* n1w  = (const float*)d_in[13];
    const float* n1b  = (const float*)d_in[14];
    const float* n2w  = (const float*)d_in[15];
    const float* n2b  = (const float*)d_in[16];
    const float* n3w  = (const float*)d_in[17];
    const float* n3b  = (const float*)d_in[18];

    float* out = (float*)d_out;

    __nv_bfloat16 *qk16, *qin16, *feat16, *v16, *x16, *h16, *w16;
    float *x32;
    cudaGetSymbolAddress((void**)&qk16, g_qk16);
    cudaGetSymbolAddress((void**)&qin16, g_qin16);
    cudaGetSymbolAddress((void**)&feat16, g_feat16);
    cudaGetSymbolAddress((void**)&v16, g_v16);
    cudaGetSymbolAddress((void**)&x16, g_x16);
    cudaGetSymbolAddress((void**)&h16, g_h16);
    cudaGetSymbolAddress((void**)&w16, g_w16);
    cudaGetSymbolAddress((void**)&x32, g_x32);

    cudaFuncSetAttribute((const void*)gemm_bf16_kernel<__nv_bfloat16, false>,
                         cudaFuncAttributeMaxDynamicSharedMemorySize, GEMM_SMEM);
    cudaFuncSetAttribute((const void*)gemm_bf16_kernel<__nv_bfloat16, true>,
                         cudaFuncAttributeMaxDynamicSharedMemorySize, GEMM_SMEM);
    cudaFuncSetAttribute((const void*)gemm_op_ln1_kernel,
                         cudaFuncAttributeMaxDynamicSharedMemorySize, FUSED_SMEM);
    cudaFuncSetAttribute((const void*)gemm_ffn_ln23_kernel,
                         cudaFuncAttributeMaxDynamicSharedMemorySize, FUSED_SMEM);

    // Pre-convert weights to bf16
    cvt_kernel<<<(221184 / 4 + 255) / 256, 256>>>(ipw, w16 + IPW_OFF, 221184 / 4);
    cvt_kernel<<<(73728 / 4 + 255) / 256, 256>>>(opw, w16 + OPW_OFF, 73728 / 4);
    cvt_kernel<<<(294912 / 4 + 255) / 256, 256>>>(l1w, w16 + L1W_OFF, 294912 / 4);
    cvt_kernel<<<(294912 / 4 + 255) / 256, 256>>>(l2w, w16 + L2W_OFF, 294912 / 4);

    const int TOT4 = NVOX * (CDIM / 4);
    dim3 ggrid((TOT4 + 255) / 256);
    dim3 gridQK(2 * CDIM / 64, NVOX / 256);   // (6, 576)
    dim3 grid192(CDIM / 64, NVOX / 256);      // (3, 576)
    dim3 grid768(DFF / 64, NVOX / 256);       // (12, 576)
    dim3 fgrid(NVOX / 64);                    // 2304

    for (int i = 0; i < 2; i++) {
        const __nv_bfloat16* Wqk = w16 + IPW_OFF + (size_t)i * 3 * CDIM * CDIM;
        const __nv_bfloat16* Wv = Wqk + 2 * CDIM * CDIM;
        const float* bqk = ipb + (size_t)i * 3 * CDIM;
        const float* bv = bqk + 2 * CDIM;
        const float* posL = pos + (size_t)i * NVOX * CDIM;
        const float* cur = (i == 0) ? src : out;

        // 1. gather -> bf16 qin, feat
        gather_kernel<<<ggrid, 256>>>(cur, posL, inds, bid, i, qin16, feat16);

        // 2. QK fused projection (Nc=384) and V projection
        gemm_bf16_kernel<__nv_bfloat16, false><<<gridQK, 256, GEMM_SMEM>>>(
            qin16, Wqk, bqk, qk16, CDIM, 2 * CDIM);
        gemm_bf16_kernel<__nv_bfloat16, false><<<grid192, 256, GEMM_SMEM>>>(
            feat16, Wv, bv, v16, CDIM, CDIM);

        // 3. attention -> qin16
        attn_kernel<<<NSET, 288>>>(qk16, v16, qin16);

        // 4. fused out_proj + scatter + residual + LN1 -> x32, x16
        gemm_op_ln1_kernel<<<fgrid, 256, FUSED_SMEM>>>(
            qin16, w16 + OPW_OFF + (size_t)i * CDIM * CDIM, opb + (size_t)i * CDIM,
            cur, inds, bid, i, n1w + i * CDIM, n1b + i * CDIM, x32, x16);

        // 5. FFN lin1 + relu -> h16
        gemm_bf16_kernel<__nv_bfloat16, true><<<grid768, 256, GEMM_SMEM>>>(
            x16, w16 + L1W_OFF + (size_t)i * DFF * CDIM, l1b + (size_t)i * DFF,
            h16, CDIM, DFF);

        // 6. fused lin2 + LN2 + LN3 -> out
        gemm_ffn_ln23_kernel<<<fgrid, 256, FUSED_SMEM>>>(
            h16, w16 + L2W_OFF + (size_t)i * CDIM * DFF, l2b + (size_t)i * CDIM,
            x32, cur, n2w + i * CDIM, n2b + i * CDIM,
            n3w + i * CDIM, n3b + i * CDIM, out);
    }
}

// round 9
// speedup vs baseline: 5.0667x; 1.0263x over previous
#include <cuda_runtime.h>
#include <cuda_bf16.h>
#include <math.h>
#include <stdint.h>

// Problem constants
#define NVOX 147456
#define CDIM 192
#define NH 8
#define DH 24
#define DFF 768
#define SETSZ 36
#define NSET 4096

// ---------------------------------------------------------------------------
// Scratch (device globals)
// ---------------------------------------------------------------------------
__device__ __nv_bfloat16 g_qk16[(size_t)NVOX * 2 * CDIM];  // Q|K voxel-order (stride 384)
__device__ __nv_bfloat16 g_qin16[(size_t)NVOX * CDIM];     // q_in (voxel) / attn out (set)
__device__ __nv_bfloat16 g_feat16[(size_t)NVOX * CDIM];    // bf16(cur), voxel order
__device__ __nv_bfloat16 g_v16[(size_t)NVOX * CDIM];       // V, voxel order
__device__ __nv_bfloat16 g_x16[(size_t)NVOX * CDIM];
__device__ __nv_bfloat16 g_h16[(size_t)NVOX * DFF];
__device__ float g_x32[(size_t)NVOX * CDIM];   // post-LN1 x (fp32)
// bf16 weights: [ipw | opw | l1w | l2w]
#define IPW_OFF 0
#define OPW_OFF 221184
#define L1W_OFF 294912
#define L2W_OFF 589824
#define W16_TOT 884736
__device__ __nv_bfloat16 g_w16[W16_TOT];

// ---------------------------------------------------------------------------
// mma.sync helpers
// ---------------------------------------------------------------------------
__device__ __forceinline__ void cp16(uint32_t dst, const void* src) {
    asm volatile("cp.async.cg.shared.global [%0], [%1], 16;\n" :: "r"(dst), "l"(src));
}
__device__ __forceinline__ void ldsm4(uint32_t* r, uint32_t addr) {
    asm volatile("ldmatrix.sync.aligned.m8n8.x4.shared.b16 {%0,%1,%2,%3}, [%4];"
                 : "=r"(r[0]), "=r"(r[1]), "=r"(r[2]), "=r"(r[3]) : "r"(addr));
}
__device__ __forceinline__ void mma_bf16(float* c, const uint32_t* a, const uint32_t* b) {
    asm volatile(
        "mma.sync.aligned.m16n8k16.row.col.f32.bf16.bf16.f32 "
        "{%0,%1,%2,%3},{%4,%5,%6,%7},{%8,%9},{%0,%1,%2,%3};"
        : "+f"(c[0]), "+f"(c[1]), "+f"(c[2]), "+f"(c[3])
        : "r"(a[0]), "r"(a[1]), "r"(a[2]), "r"(a[3]), "r"(b[0]), "r"(b[1]));
}
// Last chunk waits for its OWN group (wait_group 0); earlier leave prefetch in flight.
__device__ __forceinline__ void cp_wait(bool last) {
    if (last) asm volatile("cp.async.wait_group 0;" ::: "memory");
    else      asm volatile("cp.async.wait_group 1;" ::: "memory");
}

// ---------------------------------------------------------------------------
// Plain GEMM mainloop body (tile 256x64x32, 8 warps 4m x 2n, 3-stage).
// ---------------------------------------------------------------------------
#define GA_STAGE 16384
#define GB_STAGE 4096
#define GB_BASE  (3 * GA_STAGE)
#define GEMM_SMEM (3 * GA_STAGE + 3 * GB_STAGE)  // 61440

#define PLAIN_MAINLOOP(Aptr, Wptr, Kval)                                          \
    float acc[4][4][4];                                                           \
    _Pragma("unroll")                                                             \
    for (int mt = 0; mt < 4; mt++)                                                \
        _Pragma("unroll")                                                         \
        for (int nt = 0; nt < 4; nt++)                                            \
            _Pragma("unroll")                                                     \
            for (int r = 0; r < 4; r++) acc[mt][nt][r] = 0.f;                     \
    auto stage = [&](int kt, int buf) {                                           \
        const int k0 = kt * 32;                                                   \
        const uint32_t aB = sbase + buf * GA_STAGE;                               \
        const uint32_t bB = sbase + GB_BASE + buf * GB_STAGE;                     \
        _Pragma("unroll")                                                         \
        for (int i = 0; i < 4; i++) {                                             \
            int idx = i * 256 + tid;                                              \
            int row = idx >> 2, ch = idx & 3;                                     \
            cp16(aB + row * 64 + ((ch ^ ((row >> 1) & 3)) * 16),                  \
                 (Aptr) + (size_t)(m0 + row) * (Kval) + k0 + ch * 8);             \
        }                                                                         \
        {                                                                         \
            int row = tid >> 2, ch = tid & 3;                                     \
            cp16(bB + row * 64 + ((ch ^ ((row >> 1) & 3)) * 16),                  \
                 (Wptr) + (size_t)(n0 + row) * (Kval) + k0 + ch * 8);             \
        }                                                                         \
        asm volatile("cp.async.commit_group;" ::: "memory");                      \
    };                                                                            \
    const int nk = (Kval) >> 5;                                                   \
    stage(0, 0);                                                                  \
    stage(1, 1);                                                                  \
    for (int t = 0; t < nk; t++) {                                                \
        const int buf = t % 3;                                                    \
        cp_wait(t == nk - 1);                                                     \
        __syncthreads();                                                          \
        const uint32_t aB = sbase + buf * GA_STAGE;                               \
        const uint32_t bB = sbase + GB_BASE + buf * GB_STAGE;                     \
        _Pragma("unroll")                                                         \
        for (int ks = 0; ks < 2; ks++) {                                          \
            uint32_t af[4][4], bf[4][2];                                          \
            _Pragma("unroll")                                                     \
            for (int mt = 0; mt < 4; mt++) {                                      \
                int row = wm + mt * 16 + (lane & 15);                             \
                int ch = ks * 2 + (lane >> 4);                                    \
                ldsm4(af[mt], aB + row * 64 + ((ch ^ ((row >> 1) & 3)) * 16));    \
            }                                                                     \
            _Pragma("unroll")                                                     \
            for (int p = 0; p < 2; p++) {                                         \
                int row = wn + p * 16 + ((lane >> 4) << 3) + (lane & 7);          \
                int ch = ks * 2 + ((lane >> 3) & 1);                              \
                uint32_t r4[4];                                                   \
                ldsm4(r4, bB + row * 64 + ((ch ^ ((row >> 1) & 3)) * 16));        \
                bf[p * 2 + 0][0] = r4[0]; bf[p * 2 + 0][1] = r4[1];               \
                bf[p * 2 + 1][0] = r4[2]; bf[p * 2 + 1][1] = r4[3];               \
            }                                                                     \
            _Pragma("unroll")                                                     \
            for (int mt = 0; mt < 4; mt++)                                        \
                _Pragma("unroll")                                                 \
                for (int nt = 0; nt < 4; nt++)                                    \
                    mma_bf16(acc[mt][nt], af[mt], bf[nt]);                        \
        }                                                                         \
        __syncthreads();                                                          \
        if (t + 2 < nk) stage(t + 2, (t + 2) % 3);                                \
    }

// ---------------------------------------------------------------------------
// Plain bf16 GEMM (lin1): D[M,Nc] = A @ W^T + bias (opt ReLU)
// ---------------------------------------------------------------------------
template <typename OutT, bool RELU>
__global__ __launch_bounds__(256) void gemm_bf16_kernel(
        const __nv_bfloat16* __restrict__ A,
        const __nv_bfloat16* __restrict__ W,
        const float* __restrict__ bias,
        OutT* __restrict__ D,
        int K, int Nc) {
    extern __shared__ unsigned char smem[];
    const uint32_t sbase = (uint32_t)__cvta_generic_to_shared(smem);
    const int tid = threadIdx.x;
    const int lane = tid & 31;
    const int wid = tid >> 5;
    const int wm = (wid & 3) * 64;
    const int wn = (wid >> 2) * 32;
    const int m0 = blockIdx.y * 256;
    const int n0 = blockIdx.x * 64;

    PLAIN_MAINLOOP(A, W, K)

#pragma unroll
    for (int mt = 0; mt < 4; mt++) {
#pragma unroll
        for (int nt = 0; nt < 4; nt++) {
            int m = m0 + wm + mt * 16 + (lane >> 2);
            int n = n0 + wn + nt * 8 + (lane & 3) * 2;
            float b0 = bias[n], b1 = bias[n + 1];
            float v0 = acc[mt][nt][0] + b0;
            float v1 = acc[mt][nt][1] + b1;
            float v2 = acc[mt][nt][2] + b0;
            float v3 = acc[mt][nt][3] + b1;
            if (RELU) {
                v0 = fmaxf(v0, 0.f); v1 = fmaxf(v1, 0.f);
                v2 = fmaxf(v2, 0.f); v3 = fmaxf(v3, 0.f);
            }
            if constexpr (sizeof(OutT) == 2) {
                *reinterpret_cast<__nv_bfloat162*>((__nv_bfloat16*)D + (size_t)m * Nc + n) =
                    __floats2bfloat162_rn(v0, v1);
                *reinterpret_cast<__nv_bfloat162*>((__nv_bfloat16*)D + (size_t)(m + 8) * Nc + n) =
                    __floats2bfloat162_rn(v2, v3);
            } else {
                *reinterpret_cast<float2*>((float*)D + (size_t)m * Nc + n) = make_float2(v0, v1);
                *reinterpret_cast<float2*>((float*)D + (size_t)(m + 8) * Nc + n) = make_float2(v2, v3);
            }
        }
    }
}

// ---------------------------------------------------------------------------
// Merged QKV GEMM: Nc spans 576 (Wq|Wk|Wv rows contiguous).
//  n0 <  384: A = qin16, D = qk16 (stride 384, col n0)
//  n0 >= 384: A = feat16, D = v16 (stride 192, col n0-384)
// grid (9, 576). K = 192.
// ---------------------------------------------------------------------------
__global__ __launch_bounds__(256) void qkv_gemm_kernel(
        const __nv_bfloat16* __restrict__ Aq,
        const __nv_bfloat16* __restrict__ Af,
        const __nv_bfloat16* __restrict__ W,     // layer's 576x192 in_proj rows
        const float* __restrict__ bias,          // layer's 576 in_proj biases
        __nv_bfloat16* __restrict__ Dqk,
        __nv_bfloat16* __restrict__ Dv) {
    extern __shared__ unsigned char smem[];
    const uint32_t sbase = (uint32_t)__cvta_generic_to_shared(smem);
    const int tid = threadIdx.x;
    const int lane = tid & 31;
    const int wid = tid >> 5;
    const int wm = (wid & 3) * 64;
    const int wn = (wid >> 2) * 32;
    const int m0 = blockIdx.y * 256;
    const int n0 = blockIdx.x * 64;

    const bool isV = (n0 >= 2 * CDIM);
    const __nv_bfloat16* A = isV ? Af : Aq;
    __nv_bfloat16* D = isV ? Dv : Dqk;
    const int dStride = isV ? CDIM : 2 * CDIM;
    const int dCol0 = isV ? n0 - 2 * CDIM : n0;

    PLAIN_MAINLOOP(A, W, CDIM)

#pragma unroll
    for (int mt = 0; mt < 4; mt++) {
#pragma unroll
        for (int nt = 0; nt < 4; nt++) {
            int m = m0 + wm + mt * 16 + (lane >> 2);
            int nl = wn + nt * 8 + (lane & 3) * 2;
            int n = n0 + nl;
            float b0 = bias[n], b1 = bias[n + 1];
            int nd = dCol0 + nl;
            *reinterpret_cast<__nv_bfloat162*>(D + (size_t)m * dStride + nd) =
                __floats2bfloat162_rn(acc[mt][nt][0] + b0, acc[mt][nt][1] + b1);
            *reinterpret_cast<__nv_bfloat162*>(D + (size_t)(m + 8) * dStride + nd) =
                __floats2bfloat162_rn(acc[mt][nt][2] + b0, acc[mt][nt][3] + b1);
        }
    }
}

// ---------------------------------------------------------------------------
// Fused GEMM mainloop config (tile 64 x 192, K chunks of 32, 3-stage).
// ---------------------------------------------------------------------------
#define FA_STAGE 4096
#define FB_STAGE 12288
#define FB_BASE  (3 * FA_STAGE)
#define FUSED_SMEM (3 * FA_STAGE + 3 * FB_STAGE)  // 49152

#define FUSED_MAINLOOP(Aptr, Wptr, Kval)                                              \
    float acc[2][6][4];                                                               \
    _Pragma("unroll")                                                                 \
    for (int mt = 0; mt < 2; mt++)                                                    \
        _Pragma("unroll")                                                             \
        for (int nt = 0; nt < 6; nt++)                                                \
            _Pragma("unroll")                                                         \
            for (int r = 0; r < 4; r++) acc[mt][nt][r] = 0.f;                         \
    auto stage = [&](int kt, int buf) {                                               \
        const int k0 = kt * 32;                                                       \
        {                                                                             \
            int row = tid >> 2, ch = tid & 3;                                         \
            cp16(sbase + buf * FA_STAGE + row * 64 + ((ch ^ ((row >> 1) & 3)) * 16),  \
                 (Aptr) + (size_t)(m0 + row) * (Kval) + k0 + ch * 8);                 \
        }                                                                             \
        _Pragma("unroll")                                                             \
        for (int i = 0; i < 3; i++) {                                                 \
            int idx = i * 256 + tid;                                                  \
            int row = idx >> 2, ch = idx & 3;                                         \
            cp16(sbase + FB_BASE + buf * FB_STAGE + row * 64 +                        \
                     ((ch ^ ((row >> 1) & 3)) * 16),                                  \
                 (Wptr) + (size_t)row * (Kval) + k0 + ch * 8);                        \
        }                                                                             \
        asm volatile("cp.async.commit_group;" ::: "memory");                          \
    };                                                                                \
    const int nk = (Kval) >> 5;                                                       \
    stage(0, 0);                                                                      \
    stage(1, 1);                                                                      \
    for (int t = 0; t < nk; t++) {                                                    \
        const int buf = t % 3;                                                        \
        cp_wait(t == nk - 1);                                                         \
        __syncthreads();                                                              \
        const uint32_t aB = sbase + buf * FA_STAGE;                                   \
        const uint32_t bB = sbase + FB_BASE + buf * FB_STAGE;                         \
        _Pragma("unroll")                                                             \
        for (int ks = 0; ks < 2; ks++) {                                              \
            uint32_t af[2][4], bf[6][2];                                              \
            _Pragma("unroll")                                                         \
            for (int mt = 0; mt < 2; mt++) {                                          \
                int row = wm + mt * 16 + (lane & 15);                                 \
                int ch = ks * 2 + (lane >> 4);                                        \
                ldsm4(af[mt], aB + row * 64 + ((ch ^ ((row >> 1) & 3)) * 16));        \
            }                                                                         \
            _Pragma("unroll")                                                         \
            for (int p = 0; p < 3; p++) {                                             \
                int row = wn + p * 16 + ((lane >> 4) << 3) + (lane & 7);              \
                int ch = ks * 2 + ((lane >> 3) & 1);                                  \
                uint32_t r4[4];                                                       \
                ldsm4(r4, bB + row * 64 + ((ch ^ ((row >> 1) & 3)) * 16));            \
                bf[p * 2 + 0][0] = r4[0]; bf[p * 2 + 0][1] = r4[1];                   \
                bf[p * 2 + 1][0] = r4[2]; bf[p * 2 + 1][1] = r4[3];                   \
            }                                                                         \
            _Pragma("unroll")                                                         \
            for (int mt = 0; mt < 2; mt++)                                            \
                _Pragma("unroll")                                                     \
                for (int nt = 0; nt < 6; nt++)                                        \
                    mma_bf16(acc[mt][nt], af[mt], bf[nt]);                            \
        }                                                                             \
        __syncthreads();                                                              \
        if (t + 2 < nk) stage(t + 2, (t + 2) % 3);                                    \
    }

// ---------------------------------------------------------------------------
// Fused out_proj + scatter + residual + LN1.
// ---------------------------------------------------------------------------
__global__ __launch_bounds__(256) void gemm_op_ln1_kernel(
        const __nv_bfloat16* __restrict__ A,
        const __nv_bfloat16* __restrict__ W,
        const float* __restrict__ bias,
        const float* __restrict__ cur,
        const int* __restrict__ inds_all, const int* __restrict__ block_id, int layer,
        const float* __restrict__ lnw, const float* __restrict__ lnb,
        float* __restrict__ x32, __nv_bfloat16* __restrict__ x16) {
    extern __shared__ unsigned char smem[];
    const uint32_t sbase = (uint32_t)__cvta_generic_to_shared(smem);
    const int tid = threadIdx.x;
    const int lane = tid & 31;
    const int wid = tid >> 5;
    const int wm = (wid & 1) * 32;
    const int wn = (wid >> 1) * 48;
    const int m0 = blockIdx.x * 64;

    FUSED_MAINLOOP(A, W, CDIM)

    float* stats = reinterpret_cast<float*>(smem);
    const int gid = lane >> 2, tig = lane & 3;
    const int shift = block_id[0] & 1;
    const int* ip = inds_all + ((size_t)shift * 2 + layer) * NVOX;
    int vrow[2][2];
#pragma unroll
    for (int mt = 0; mt < 2; mt++) {
#pragma unroll
        for (int mm = 0; mm < 2; mm++) {
            int rloc = wm + mt * 16 + mm * 8 + gid;
            int v = ip[m0 + rloc];
            vrow[mt][mm] = v;
            float s = 0.f, s2 = 0.f;
#pragma unroll
            for (int nt = 0; nt < 6; nt++) {
                int n = wn + nt * 8 + tig * 2;
                float2 c = *reinterpret_cast<const float2*>(cur + (size_t)v * CDIM + n);
                float a0 = acc[mt][nt][mm * 2]     + bias[n]     + c.x;
                float a1 = acc[mt][nt][mm * 2 + 1] + bias[n + 1] + c.y;
                acc[mt][nt][mm * 2] = a0; acc[mt][nt][mm * 2 + 1] = a1;
                s += a0 + a1; s2 += a0 * a0 + a1 * a1;
            }
            s  += __shfl_xor_sync(0xffffffffu, s, 1);  s  += __shfl_xor_sync(0xffffffffu, s, 2);
            s2 += __shfl_xor_sync(0xffffffffu, s2, 1); s2 += __shfl_xor_sync(0xffffffffu, s2, 2);
            if (tig == 0) {
                stats[((wid >> 1) * 64 + rloc) * 2]     = s;
                stats[((wid >> 1) * 64 + rloc) * 2 + 1] = s2;
            }
        }
    }
    __syncthreads();
#pragma unroll
    for (int mt = 0; mt < 2; mt++) {
#pragma unroll
        for (int mm = 0; mm < 2; mm++) {
            int rloc = wm + mt * 16 + mm * 8 + gid;
            int v = vrow[mt][mm];
            float S = 0.f, S2 = 0.f;
#pragma unroll
            for (int g = 0; g < 4; g++) {
                S  += stats[(g * 64 + rloc) * 2];
                S2 += stats[(g * 64 + rloc) * 2 + 1];
            }
            float mean = S * (1.0f / CDIM);
            float var = S2 * (1.0f / CDIM) - mean * mean;
            float rs = rsqrtf(var + 1e-5f);
#pragma unroll
            for (int nt = 0; nt < 6; nt++) {
                int n = wn + nt * 8 + tig * 2;
                float o0 = (acc[mt][nt][mm * 2]     - mean) * rs * lnw[n]     + lnb[n];
                float o1 = (acc[mt][nt][mm * 2 + 1] - mean) * rs * lnw[n + 1] + lnb[n + 1];
                *reinterpret_cast<float2*>(x32 + (size_t)v * CDIM + n) = make_float2(o0, o1);
                *reinterpret_cast<__nv_bfloat162*>(x16 + (size_t)v * CDIM + n) =
                    __floats2bfloat162_rn(o0, o1);
            }
        }
    }
}

// ---------------------------------------------------------------------------
// Fused lin2 + LN2 + LN3 (voxel-order rows).
// ---------------------------------------------------------------------------
__global__ __launch_bounds__(256) void gemm_ffn_ln23_kernel(
        const __nv_bfloat16* __restrict__ A,
        const __nv_bfloat16* __restrict__ W,
        const float* __restrict__ bias,
        const float* __restrict__ x32,
        const float* __restrict__ cur,
        const float* __restrict__ w2, const float* __restrict__ b2,
        const float* __restrict__ w3, const float* __restrict__ b3,
        float* __restrict__ outp) {
    extern __shared__ unsigned char smem[];
    const uint32_t sbase = (uint32_t)__cvta_generic_to_shared(smem);
    const int tid = threadIdx.x;
    const int lane = tid & 31;
    const int wid = tid >> 5;
    const int wm = (wid & 1) * 32;
    const int wn = (wid >> 1) * 48;
    const int m0 = blockIdx.x * 64;

    FUSED_MAINLOOP(A, W, DFF)

    float* stats = reinterpret_cast<float*>(smem);
    const int gid = lane >> 2, tig = lane & 3;

#pragma unroll
    for (int mt = 0; mt < 2; mt++) {
#pragma unroll
        for (int mm = 0; mm < 2; mm++) {
            int rloc = wm + mt * 16 + mm * 8 + gid;
            int v = m0 + rloc;
            float s = 0.f, s2 = 0.f;
#pragma unroll
            for (int nt = 0; nt < 6; nt++) {
                int n = wn + nt * 8 + tig * 2;
                float2 xr = *reinterpret_cast<const float2*>(x32 + (size_t)v * CDIM + n);
                float a0 = acc[mt][nt][mm * 2]     + bias[n]     + xr.x;
                float a1 = acc[mt][nt][mm * 2 + 1] + bias[n + 1] + xr.y;
                acc[mt][nt][mm * 2] = a0; acc[mt][nt][mm * 2 + 1] = a1;
                s += a0 + a1; s2 += a0 * a0 + a1 * a1;
            }
            s  += __shfl_xor_sync(0xffffffffu, s, 1);  s  += __shfl_xor_sync(0xffffffffu, s, 2);
            s2 += __shfl_xor_sync(0xffffffffu, s2, 1); s2 += __shfl_xor_sync(0xffffffffu, s2, 2);
            if (tig == 0) {
                stats[((wid >> 1) * 64 + rloc) * 2]     = s;
                stats[((wid >> 1) * 64 + rloc) * 2 + 1] = s2;
            }
        }
    }
    __syncthreads();

    float sB[2][2], s2B[2][2];
#pragma unroll
    for (int mt = 0; mt < 2; mt++) {
#pragma unroll
        for (int mm = 0; mm < 2; mm++) {
            int rloc = wm + mt * 16 + mm * 8 + gid;
            int v = m0 + rloc;
            float S = 0.f, S2 = 0.f;
#pragma unroll
            for (int g = 0; g < 4; g++) {
                S  += stats[(g * 64 + rloc) * 2];
                S2 += stats[(g * 64 + rloc) * 2 + 1];
            }
            float mean = S * (1.0f / CDIM);
            float var = S2 * (1.0f / CDIM) - mean * mean;
            float rs = rsqrtf(var + 1e-5f);
            float s = 0.f, s2 = 0.f;
#pragma unroll
            for (int nt = 0; nt < 6; nt++) {
                int n = wn + nt * 8 + tig * 2;
                float2 cv = *reinterpret_cast<const float2*>(cur + (size_t)v * CDIM + n);
                float t0 = (acc[mt][nt][mm * 2]     - mean) * rs * w2[n]     + b2[n]     + cv.x;
                float t1 = (acc[mt][nt][mm * 2 + 1] - mean) * rs * w2[n + 1] + b2[n + 1] + cv.y;
                acc[mt][nt][mm * 2] = t0; acc[mt][nt][mm * 2 + 1] = t1;
                s += t0 + t1; s2 += t0 * t0 + t1 * t1;
            }
            s  += __shfl_xor_sync(0xffffffffu, s, 1);  s  += __shfl_xor_sync(0xffffffffu, s, 2);
            s2 += __shfl_xor_sync(0xffffffffu, s2, 1); s2 += __shfl_xor_sync(0xffffffffu, s2, 2);
            sB[mt][mm] = s; s2B[mt][mm] = s2;
        }
    }
    __syncthreads();
#pragma unroll
    for (int mt = 0; mt < 2; mt++)
#pragma unroll
        for (int mm = 0; mm < 2; mm++) {
            int rloc = wm + mt * 16 + mm * 8 + gid;
            if (tig == 0) {
                stats[((wid >> 1) * 64 + rloc) * 2]     = sB[mt][mm];
                stats[((wid >> 1) * 64 + rloc) * 2 + 1] = s2B[mt][mm];
            }
        }
    __syncthreads();

#pragma unroll
    for (int mt = 0; mt < 2; mt++) {
#pragma unroll
        for (int mm = 0; mm < 2; mm++) {
            int rloc = wm + mt * 16 + mm * 8 + gid;
            int v = m0 + rloc;
            float S = 0.f, S2 = 0.f;
#pragma unroll
            for (int g = 0; g < 4; g++) {
                S  += stats[(g * 64 + rloc) * 2];
                S2 += stats[(g * 64 + rloc) * 2 + 1];
            }
            float mean = S * (1.0f / CDIM);
            float var = S2 * (1.0f / CDIM) - mean * mean;
            float rs = rsqrtf(var + 1e-5f);
#pragma unroll
            for (int nt = 0; nt < 6; nt++) {
                int n = wn + nt * 8 + tig * 2;
                float o0 = (acc[mt][nt][mm * 2]     - mean) * rs * w3[n]     + b3[n];
                float o1 = (acc[mt][nt][mm * 2 + 1] - mean) * rs * w3[n + 1] + b3[n + 1];
                *reinterpret_cast<float2*>(outp + (size_t)v * CDIM + n) = make_float2(o0, o1);
            }
        }
    }
}

// ---------------------------------------------------------------------------
// Single merged weight converter (all 4 weight blocks in one launch)
// ---------------------------------------------------------------------------
__global__ void cvt_all_kernel(const float* __restrict__ ipw,
                               const float* __restrict__ opw,
                               const float* __restrict__ l1w,
                               const float* __restrict__ l2w,
                               __nv_bfloat16* __restrict__ dst) {
    int i = blockIdx.x * blockDim.x + threadIdx.x;  // float4 index
    const int N4 = W16_TOT / 4;
    if (i >= N4) return;
    int e = i * 4;
    const float* src;
    int off;
    if (e < OPW_OFF)      { src = ipw; off = e - IPW_OFF; }
    else if (e < L1W_OFF) { src = opw; off = e - OPW_OFF; }
    else if (e < L2W_OFF) { src = l1w; off = e - L1W_OFF; }
    else                  { src = l2w; off = e - L2W_OFF; }
    float4 v = *reinterpret_cast<const float4*>(src + off);
    reinterpret_cast<__nv_bfloat162*>(dst)[i * 2 + 0] = __floats2bfloat162_rn(v.x, v.y);
    reinterpret_cast<__nv_bfloat162*>(dst)[i * 2 + 1] = __floats2bfloat162_rn(v.z, v.w);
}

// ---------------------------------------------------------------------------
// Prep (coalesced, voxel order): qin16 = bf16(cur+pos); feat16 = bf16(cur)
// ---------------------------------------------------------------------------
__global__ void prep_kernel(const float* __restrict__ cur,
                            const float* __restrict__ pos,
                            __nv_bfloat16* __restrict__ qin,
                            __nv_bfloat16* __restrict__ feat) {
    int gid = blockIdx.x * blockDim.x + threadIdx.x;
    const int TOT = NVOX * (CDIM / 4);
    if (gid >= TOT) return;
    float4 f = reinterpret_cast<const float4*>(cur)[gid];
    float4 pp = reinterpret_cast<const float4*>(pos)[gid];
    __nv_bfloat162* f2 = reinterpret_cast<__nv_bfloat162*>(feat);
    __nv_bfloat162* q2 = reinterpret_cast<__nv_bfloat162*>(qin);
    f2[gid * 2 + 0] = __floats2bfloat162_rn(f.x, f.y);
    f2[gid * 2 + 1] = __floats2bfloat162_rn(f.z, f.w);
    q2[gid * 2 + 0] = __floats2bfloat162_rn(f.x + pp.x, f.y + pp.y);
    q2[gid * 2 + 1] = __floats2bfloat162_rn(f.z + pp.z, f.w + pp.w);
}

// ---------------------------------------------------------------------------
// Attention: one block per set, 288 threads. Inputs voxel-ordered (indirect
// row gather via inds); output SET-ordered (row p = s*36+l).
// ---------------------------------------------------------------------------
__global__ __launch_bounds__(288) void attn_kernel(const __nv_bfloat16* __restrict__ qk,
                                                   const __nv_bfloat16* __restrict__ v,
                                                   const int* __restrict__ inds_all,
                                                   const int* __restrict__ block_id,
                                                   int layer,
                                                   __nv_bfloat16* __restrict__ o) {
    __shared__ __nv_bfloat16 qks[SETSZ * 384];
    __shared__ __nv_bfloat16 vs[SETSZ * CDIM];
    __shared__ int vids[SETSZ];
    int s = blockIdx.x;
    int tid = threadIdx.x;

    if (tid < SETSZ) {
        int shift = block_id[0] & 1;
        vids[tid] = inds_all[((size_t)shift * 2 + layer) * NVOX + s * SETSZ + tid];
    }
    __syncthreads();

    // Gather rows: qk row = 48 uint4, v row = 24 uint4
    const uint4* qk4 = reinterpret_cast<const uint4*>(qk);
    const uint4* v4 = reinterpret_cast<const uint4*>(v);
    for (int idx = tid; idx < SETSZ * 48; idx += 288) {
        int row = idx / 48, c = idx % 48;
        reinterpret_cast<uint4*>(qks)[row * 48 + c] = qk4[(size_t)vids[row] * 48 + c];
    }
    for (int idx = tid; idx < SETSZ * 24; idx += 288) {
        int row = idx / 24, c = idx % 24;
        reinterpret_cast<uint4*>(vs)[row * 24 + c] = v4[(size_t)vids[row] * 24 + c];
    }
    __syncthreads();

    int l = tid % SETSZ;
    int h = tid / SETSZ;

    float qr[DH];
#pragma unroll
    for (int d = 0; d < DH; d++) qr[d] = __bfloat162float(qks[l * 384 + h * DH + d]);

    const float scale = 0.20412414523193154f;
    float sc[SETSZ];
    float mx = -1e30f;
#pragma unroll 4
    for (int m = 0; m < SETSZ; m++) {
        const __nv_bfloat16* kr = qks + m * 384 + 192 + h * DH;
        float dot = 0.f;
#pragma unroll
        for (int d = 0; d < DH; d++) dot += qr[d] * __bfloat162float(kr[d]);
        dot *= scale;
        sc[m] = dot;
        mx = fmaxf(mx, dot);
    }
    float sum = 0.f;
#pragma unroll 4
    for (int m = 0; m < SETSZ; m++) {
        sc[m] = expf(sc[m] - mx);
        sum += sc[m];
    }
    float inv = 1.0f / sum;
    __nv_bfloat162* o2 = reinterpret_cast<__nv_bfloat162*>(
        o + (size_t)s * SETSZ * CDIM + l * CDIM + h * DH);
#pragma unroll
    for (int d2 = 0; d2 < DH / 2; d2++) {
        float a0 = 0.f, a1 = 0.f;
#pragma unroll 4
        for (int m = 0; m < SETSZ; m++) {
            float p = sc[m];
            a0 += p * __bfloat162float(vs[m * CDIM + h * DH + d2 * 2]);
            a1 += p * __bfloat162float(vs[m * CDIM + h * DH + d2 * 2 + 1]);
        }
        o2[d2] = __floats2bfloat162_rn(a0 * inv, a1 * inv);
    }
}

// ---------------------------------------------------------------------------
// Host orchestration
// ---------------------------------------------------------------------------
extern "C" void kernel_launch(void* const* d_in, const int* in_sizes, int n_in,
                              void* d_out, int out_size) {
    (void)in_sizes; (void)n_in; (void)out_size;
    const float* src  = (const float*)d_in[0];
    const int*   inds = (const int*)d_in[1];
    const float* pos  = (const float*)d_in[3];
    const int*   bid  = (const int*)d_in[4];
    const float* ipw  = (const float*)d_in[5];
    const float* ipb  = (const float*)d_in[6];
    const float* opw  = (const float*)d_in[7];
    const float* opb  = (const float*)d_in[8];
    const float* l1w  = (const float*)d_in[9];
    const float* l1b  = (const float*)d_in[10];
    const float* l2w  = (const float*)d_in[11];
    const float* l2b  = (const float*)d_in[12];
    const float* n1w  = (const float*)d_in[13];
    const float* n1b  = (const float*)d_in[14];
    const float* n2w  = (const float*)d_in[15];
    const float* n2b  = (const float*)d_in[16];
    const float* n3w  = (const float*)d_in[17];
    const float* n3b  = (const float*)d_in[18];

    float* out = (float*)d_out;

    __nv_bfloat16 *qk16, *qin16, *feat16, *v16, *x16, *h16, *w16;
    float *x32;
    cudaGetSymbolAddress((void**)&qk16, g_qk16);
    cudaGetSymbolAddress((void**)&qin16, g_qin16);
    cudaGetSymbolAddress((void**)&feat16, g_feat16);
    cudaGetSymbolAddress((void**)&v16, g_v16);
    cudaGetSymbolAddress((void**)&x16, g_x16);
    cudaGetSymbolAddress((void**)&h16, g_h16);
    cudaGetSymbolAddress((void**)&w16, g_w16);
    cudaGetSymbolAddress((void**)&x32, g_x32);

    cudaFuncSetAttribute((const void*)gemm_bf16_kernel<__nv_bfloat16, true>,
                         cudaFuncAttributeMaxDynamicSharedMemorySize, GEMM_SMEM);
    cudaFuncSetAttribute((const void*)qkv_gemm_kernel,
                         cudaFuncAttributeMaxDynamicSharedMemorySize, GEMM_SMEM);
    cudaFuncSetAttribute((const void*)gemm_op_ln1_kernel,
                         cudaFuncAttributeMaxDynamicSharedMemorySize, FUSED_SMEM);
    cudaFuncSetAttribute((const void*)gemm_ffn_ln23_kernel,
                         cudaFuncAttributeMaxDynamicSharedMemorySize, FUSED_SMEM);

    // 1 launch: all weights -> bf16
    cvt_all_kernel<<<(W16_TOT / 4 + 255) / 256, 256>>>(ipw, opw, l1w, l2w, w16);

    const int TOT4 = NVOX * (CDIM / 4);
    dim3 pgrid((TOT4 + 255) / 256);
    dim3 gridQKV(9, NVOX / 256);              // 576 rows x 9 n-blocks (Nc=576)
    dim3 grid768(DFF / 64, NVOX / 256);       // (12, 576)
    dim3 fgrid(NVOX / 64);                    // 2304

    for (int i = 0; i < 2; i++) {
        const __nv_bfloat16* Wqkv = w16 + IPW_OFF + (size_t)i * 3 * CDIM * CDIM;
        const float* bqkv = ipb + (size_t)i * 3 * CDIM;
        const float* posL = pos + (size_t)i * NVOX * CDIM;
        const float* cur = (i == 0) ? src : out;

        // 1. prep (coalesced): qin16 = bf16(cur+pos), feat16 = bf16(cur)
        prep_kernel<<<pgrid, 256>>>(cur, posL, qin16, feat16);

        // 2. merged QKV projection (voxel order)
        qkv_gemm_kernel<<<gridQKV, 256, GEMM_SMEM>>>(
            qin16, feat16, Wqkv, bqkv, qk16, v16);

        // 3. attention (indirect gather) -> qin16 (set order)
        attn_kernel<<<NSET, 288>>>(qk16, v16, inds, bid, i, qin16);

        // 4. fused out_proj + scatter + residual + LN1 -> x32, x16 (voxel order)
        gemm_op_ln1_kernel<<<fgrid, 256, FUSED_SMEM>>>(
            qin16, w16 + OPW_OFF + (size_t)i * CDIM * CDIM, opb + (size_t)i * CDIM,
            cur, inds, bid, i, n1w + i * CDIM, n1b + i * CDIM, x32, x16);

        // 5. FFN lin1 + relu -> h16
        gemm_bf16_kernel<__nv_bfloat16, true><<<grid768, 256, GEMM_SMEM>>>(
            x16, w16 + L1W_OFF + (size_t)i * DFF * CDIM, l1b + (size_t)i * DFF,
            h16, CDIM, DFF);

        // 6. fused lin2 + LN2 + LN3 -> out
        gemm_ffn_ln23_kernel<<<fgrid, 256, FUSED_SMEM>>>(
            h16, w16 + L2W_OFF + (size_t)i * CDIM * DFF, l2b + (size_t)i * CDIM,
            x32, cur, n2w + i * CDIM, n2b + i * CDIM,
            n3w + i * CDIM, n3b + i * CDIM, out);
    }
}

// round 10
// speedup vs baseline: 6.1491x; 1.2136x over previous
#include <cuda_runtime.h>
#include <cuda_bf16.h>
#include <math.h>
#include <stdint.h>

// Problem constants
#define NVOX 147456
#define CDIM 192
#define NH 8
#define DH 24
#define DFF 768
#define SETSZ 36
#define NSET 4096

// ---------------------------------------------------------------------------
// Scratch (device globals)
// ---------------------------------------------------------------------------
__device__ __nv_bfloat16 g_qk16[(size_t)NVOX * 2 * CDIM];  // Q|K voxel-order (stride 384)
__device__ __nv_bfloat16 g_qin16[(size_t)NVOX * CDIM];     // q_in (voxel) / attn out (set)
__device__ __nv_bfloat16 g_feat16[(size_t)NVOX * CDIM];    // bf16(cur), voxel order
__device__ __nv_bfloat16 g_v16[(size_t)NVOX * CDIM];       // V, voxel order
__device__ __nv_bfloat16 g_x16[(size_t)NVOX * CDIM];
__device__ __nv_bfloat16 g_h16[(size_t)NVOX * DFF];
__device__ float g_x32[(size_t)NVOX * CDIM];   // post-LN1 x (fp32)
// bf16 weights: [ipw | opw | l1w | l2w]
#define IPW_OFF 0
#define OPW_OFF 221184
#define L1W_OFF 294912
#define L2W_OFF 589824
#define W16_TOT 884736
__device__ __nv_bfloat16 g_w16[W16_TOT];

// ---------------------------------------------------------------------------
// mma.sync helpers
// ---------------------------------------------------------------------------
__device__ __forceinline__ void cp16(uint32_t dst, const void* src) {
    asm volatile("cp.async.cg.shared.global [%0], [%1], 16;\n" :: "r"(dst), "l"(src));
}
__device__ __forceinline__ void ldsm4(uint32_t* r, uint32_t addr) {
    asm volatile("ldmatrix.sync.aligned.m8n8.x4.shared.b16 {%0,%1,%2,%3}, [%4];"
                 : "=r"(r[0]), "=r"(r[1]), "=r"(r[2]), "=r"(r[3]) : "r"(addr));
}
__device__ __forceinline__ void mma_bf16(float* c, const uint32_t* a, const uint32_t* b) {
    asm volatile(
        "mma.sync.aligned.m16n8k16.row.col.f32.bf16.bf16.f32 "
        "{%0,%1,%2,%3},{%4,%5,%6,%7},{%8,%9},{%0,%1,%2,%3};"
        : "+f"(c[0]), "+f"(c[1]), "+f"(c[2]), "+f"(c[3])
        : "r"(a[0]), "r"(a[1]), "r"(a[2]), "r"(a[3]), "r"(b[0]), "r"(b[1]));
}
// Last chunk waits for its OWN group (wait_group 0); earlier leave prefetch in flight.
__device__ __forceinline__ void cp_wait(bool last) {
    if (last) asm volatile("cp.async.wait_group 0;" ::: "memory");
    else      asm volatile("cp.async.wait_group 1;" ::: "memory");
}
// Unpack 8 bf16 (uint4) -> 8 floats
__device__ __forceinline__ void unpack8(uint4 u, float* f) {
    uint32_t w[4] = {u.x, u.y, u.z, u.w};
#pragma unroll
    for (int j = 0; j < 4; j++) {
        float2 t = __bfloat1622float2(*reinterpret_cast<__nv_bfloat162*>(&w[j]));
        f[j * 2] = t.x; f[j * 2 + 1] = t.y;
    }
}

// ---------------------------------------------------------------------------
// Plain GEMM mainloop body (tile 256x64x32, 8 warps 4m x 2n, 3-stage).
// ---------------------------------------------------------------------------
#define GA_STAGE 16384
#define GB_STAGE 4096
#define GB_BASE  (3 * GA_STAGE)
#define GEMM_SMEM (3 * GA_STAGE + 3 * GB_STAGE)  // 61440

#define PLAIN_MAINLOOP(Aptr, Wptr, Kval)                                          \
    float acc[4][4][4];                                                           \
    _Pragma("unroll")                                                             \
    for (int mt = 0; mt < 4; mt++)                                                \
        _Pragma("unroll")                                                         \
        for (int nt = 0; nt < 4; nt++)                                            \
            _Pragma("unroll")                                                     \
            for (int r = 0; r < 4; r++) acc[mt][nt][r] = 0.f;                     \
    auto stage = [&](int kt, int buf) {                                           \
        const int k0 = kt * 32;                                                   \
        const uint32_t aB = sbase + buf * GA_STAGE;                               \
        const uint32_t bB = sbase + GB_BASE + buf * GB_STAGE;                     \
        _Pragma("unroll")                                                         \
        for (int i = 0; i < 4; i++) {                                             \
            int idx = i * 256 + tid;                                              \
            int row = idx >> 2, ch = idx & 3;                                     \
            cp16(aB + row * 64 + ((ch ^ ((row >> 1) & 3)) * 16),                  \
                 (Aptr) + (size_t)(m0 + row) * (Kval) + k0 + ch * 8);             \
        }                                                                         \
        {                                                                         \
            int row = tid >> 2, ch = tid & 3;                                     \
            cp16(bB + row * 64 + ((ch ^ ((row >> 1) & 3)) * 16),                  \
                 (Wptr) + (size_t)(n0 + row) * (Kval) + k0 + ch * 8);             \
        }                                                                         \
        asm volatile("cp.async.commit_group;" ::: "memory");                      \
    };                                                                            \
    const int nk = (Kval) >> 5;                                                   \
    stage(0, 0);                                                                  \
    stage(1, 1);                                                                  \
    for (int t = 0; t < nk; t++) {                                                \
        const int buf = t % 3;                                                    \
        cp_wait(t == nk - 1);                                                     \
        __syncthreads();                                                          \
        const uint32_t aB = sbase + buf * GA_STAGE;                               \
        const uint32_t bB = sbase + GB_BASE + buf * GB_STAGE;                     \
        _Pragma("unroll")                                                         \
        for (int ks = 0; ks < 2; ks++) {                                          \
            uint32_t af[4][4], bf[4][2];                                          \
            _Pragma("unroll")                                                     \
            for (int mt = 0; mt < 4; mt++) {                                      \
                int row = wm + mt * 16 + (lane & 15);                             \
                int ch = ks * 2 + (lane >> 4);                                    \
                ldsm4(af[mt], aB + row * 64 + ((ch ^ ((row >> 1) & 3)) * 16));    \
            }                                                                     \
            _Pragma("unroll")                                                     \
            for (int p = 0; p < 2; p++) {                                         \
                int row = wn + p * 16 + ((lane >> 4) << 3) + (lane & 7);          \
                int ch = ks * 2 + ((lane >> 3) & 1);                              \
                uint32_t r4[4];                                                   \
                ldsm4(r4, bB + row * 64 + ((ch ^ ((row >> 1) & 3)) * 16));        \
                bf[p * 2 + 0][0] = r4[0]; bf[p * 2 + 0][1] = r4[1];               \
                bf[p * 2 + 1][0] = r4[2]; bf[p * 2 + 1][1] = r4[3];               \
            }                                                                     \
            _Pragma("unroll")                                                     \
            for (int mt = 0; mt < 4; mt++)                                        \
                _Pragma("unroll")                                                 \
                for (int nt = 0; nt < 4; nt++)                                    \
                    mma_bf16(acc[mt][nt], af[mt], bf[nt]);                        \
        }                                                                         \
        __syncthreads();                                                          \
        if (t + 2 < nk) stage(t + 2, (t + 2) % 3);                                \
    }

// ---------------------------------------------------------------------------
// Plain bf16 GEMM (lin1): D[M,Nc] = A @ W^T + bias (opt ReLU)
// ---------------------------------------------------------------------------
template <typename OutT, bool RELU>
__global__ __launch_bounds__(256) void gemm_bf16_kernel(
        const __nv_bfloat16* __restrict__ A,
        const __nv_bfloat16* __restrict__ W,
        const float* __restrict__ bias,
        OutT* __restrict__ D,
        int K, int Nc) {
    extern __shared__ unsigned char smem[];
    const uint32_t sbase = (uint32_t)__cvta_generic_to_shared(smem);
    const int tid = threadIdx.x;
    const int lane = tid & 31;
    const int wid = tid >> 5;
    const int wm = (wid & 3) * 64;
    const int wn = (wid >> 2) * 32;
    const int m0 = blockIdx.y * 256;
    const int n0 = blockIdx.x * 64;

    PLAIN_MAINLOOP(A, W, K)

#pragma unroll
    for (int mt = 0; mt < 4; mt++) {
#pragma unroll
        for (int nt = 0; nt < 4; nt++) {
            int m = m0 + wm + mt * 16 + (lane >> 2);
            int n = n0 + wn + nt * 8 + (lane & 3) * 2;
            float b0 = bias[n], b1 = bias[n + 1];
            float v0 = acc[mt][nt][0] + b0;
            float v1 = acc[mt][nt][1] + b1;
            float v2 = acc[mt][nt][2] + b0;
            float v3 = acc[mt][nt][3] + b1;
            if (RELU) {
                v0 = fmaxf(v0, 0.f); v1 = fmaxf(v1, 0.f);
                v2 = fmaxf(v2, 0.f); v3 = fmaxf(v3, 0.f);
            }
            if constexpr (sizeof(OutT) == 2) {
                *reinterpret_cast<__nv_bfloat162*>((__nv_bfloat16*)D + (size_t)m * Nc + n) =
                    __floats2bfloat162_rn(v0, v1);
                *reinterpret_cast<__nv_bfloat162*>((__nv_bfloat16*)D + (size_t)(m + 8) * Nc + n) =
                    __floats2bfloat162_rn(v2, v3);
            } else {
                *reinterpret_cast<float2*>((float*)D + (size_t)m * Nc + n) = make_float2(v0, v1);
                *reinterpret_cast<float2*>((float*)D + (size_t)(m + 8) * Nc + n) = make_float2(v2, v3);
            }
        }
    }
}

// ---------------------------------------------------------------------------
// Merged QKV GEMM: Nc spans 576 (Wq|Wk|Wv rows contiguous).
// ---------------------------------------------------------------------------
__global__ __launch_bounds__(256) void qkv_gemm_kernel(
        const __nv_bfloat16* __restrict__ Aq,
        const __nv_bfloat16* __restrict__ Af,
        const __nv_bfloat16* __restrict__ W,
        const float* __restrict__ bias,
        __nv_bfloat16* __restrict__ Dqk,
        __nv_bfloat16* __restrict__ Dv) {
    extern __shared__ unsigned char smem[];
    const uint32_t sbase = (uint32_t)__cvta_generic_to_shared(smem);
    const int tid = threadIdx.x;
    const int lane = tid & 31;
    const int wid = tid >> 5;
    const int wm = (wid & 3) * 64;
    const int wn = (wid >> 2) * 32;
    const int m0 = blockIdx.y * 256;
    const int n0 = blockIdx.x * 64;

    const bool isV = (n0 >= 2 * CDIM);
    const __nv_bfloat16* A = isV ? Af : Aq;
    __nv_bfloat16* D = isV ? Dv : Dqk;
    const int dStride = isV ? CDIM : 2 * CDIM;
    const int dCol0 = isV ? n0 - 2 * CDIM : n0;

    PLAIN_MAINLOOP(A, W, CDIM)

#pragma unroll
    for (int mt = 0; mt < 4; mt++) {
#pragma unroll
        for (int nt = 0; nt < 4; nt++) {
            int m = m0 + wm + mt * 16 + (lane >> 2);
            int nl = wn + nt * 8 + (lane & 3) * 2;
            int n = n0 + nl;
            float b0 = bias[n], b1 = bias[n + 1];
            int nd = dCol0 + nl;
            *reinterpret_cast<__nv_bfloat162*>(D + (size_t)m * dStride + nd) =
                __floats2bfloat162_rn(acc[mt][nt][0] + b0, acc[mt][nt][1] + b1);
            *reinterpret_cast<__nv_bfloat162*>(D + (size_t)(m + 8) * dStride + nd) =
                __floats2bfloat162_rn(acc[mt][nt][2] + b0, acc[mt][nt][3] + b1);
        }
    }
}

// ---------------------------------------------------------------------------
// Fused GEMM mainloop config (tile 64 x 192, K chunks of 32, 3-stage).
// ---------------------------------------------------------------------------
#define FA_STAGE 4096
#define FB_STAGE 12288
#define FB_BASE  (3 * FA_STAGE)
#define FUSED_SMEM (3 * FA_STAGE + 3 * FB_STAGE)  // 49152

#define FUSED_MAINLOOP(Aptr, Wptr, Kval)                                              \
    float acc[2][6][4];                                                               \
    _Pragma("unroll")                                                                 \
    for (int mt = 0; mt < 2; mt++)                                                    \
        _Pragma("unroll")                                                             \
        for (int nt = 0; nt < 6; nt++)                                                \
            _Pragma("unroll")                                                         \
            for (int r = 0; r < 4; r++) acc[mt][nt][r] = 0.f;                         \
    auto stage = [&](int kt, int buf) {                                               \
        const int k0 = kt * 32;                                                       \
        {                                                                             \
            int row = tid >> 2, ch = tid & 3;                                         \
            cp16(sbase + buf * FA_STAGE + row * 64 + ((ch ^ ((row >> 1) & 3)) * 16),  \
                 (Aptr) + (size_t)(m0 + row) * (Kval) + k0 + ch * 8);                 \
        }                                                                             \
        _Pragma("unroll")                                                             \
        for (int i = 0; i < 3; i++) {                                                 \
            int idx = i * 256 + tid;                                                  \
            int row = idx >> 2, ch = idx & 3;                                         \
            cp16(sbase + FB_BASE + buf * FB_STAGE + row * 64 +                        \
                     ((ch ^ ((row >> 1) & 3)) * 16),                                  \
                 (Wptr) + (size_t)row * (Kval) + k0 + ch * 8);                        \
        }                                                                             \
        asm volatile("cp.async.commit_group;" ::: "memory");                          \
    };                                                                                \
    const int nk = (Kval) >> 5;                                                       \
    stage(0, 0);                                                                      \
    stage(1, 1);                                                                      \
    for (int t = 0; t < nk; t++) {                                                    \
        const int buf = t % 3;                                                        \
        cp_wait(t == nk - 1);                                                         \
        __syncthreads();                                                              \
        const uint32_t aB = sbase + buf * FA_STAGE;                                   \
        const uint32_t bB = sbase + FB_BASE + buf * FB_STAGE;                         \
        _Pragma("unroll")                                                             \
        for (int ks = 0; ks < 2; ks++) {                                              \
            uint32_t af[2][4], bf[6][2];                                              \
            _Pragma("unroll")                                                         \
            for (int mt = 0; mt < 2; mt++) {                                          \
                int row = wm + mt * 16 + (lane & 15);                                 \
                int ch = ks * 2 + (lane >> 4);                                        \
                ldsm4(af[mt], aB + row * 64 + ((ch ^ ((row >> 1) & 3)) * 16));        \
            }                                                                         \
            _Pragma("unroll")                                                         \
            for (int p = 0; p < 3; p++) {                                             \
                int row = wn + p * 16 + ((lane >> 4) << 3) + (lane & 7);              \
                int ch = ks * 2 + ((lane >> 3) & 1);                                  \
                uint32_t r4[4];                                                       \
                ldsm4(r4, bB + row * 64 + ((ch ^ ((row >> 1) & 3)) * 16));            \
                bf[p * 2 + 0][0] = r4[0]; bf[p * 2 + 0][1] = r4[1];                   \
                bf[p * 2 + 1][0] = r4[2]; bf[p * 2 + 1][1] = r4[3];                   \
            }                                                                         \
            _Pragma("unroll")                                                         \
            for (int mt = 0; mt < 2; mt++)                                            \
                _Pragma("unroll")                                                     \
                for (int nt = 0; nt < 6; nt++)                                        \
                    mma_bf16(acc[mt][nt], af[mt], bf[nt]);                            \
        }                                                                             \
        __syncthreads();                                                              \
        if (t + 2 < nk) stage(t + 2, (t + 2) % 3);                                    \
    }

// ---------------------------------------------------------------------------
// Fused out_proj + scatter + residual + LN1.
// ---------------------------------------------------------------------------
__global__ __launch_bounds__(256) void gemm_op_ln1_kernel(
        const __nv_bfloat16* __restrict__ A,
        const __nv_bfloat16* __restrict__ W,
        const float* __restrict__ bias,
        const float* __restrict__ cur,
        const int* __restrict__ inds_all, const int* __restrict__ block_id, int layer,
        const float* __restrict__ lnw, const float* __restrict__ lnb,
        float* __restrict__ x32, __nv_bfloat16* __restrict__ x16) {
    extern __shared__ unsigned char smem[];
    const uint32_t sbase = (uint32_t)__cvta_generic_to_shared(smem);
    const int tid = threadIdx.x;
    const int lane = tid & 31;
    const int wid = tid >> 5;
    const int wm = (wid & 1) * 32;
    const int wn = (wid >> 1) * 48;
    const int m0 = blockIdx.x * 64;

    FUSED_MAINLOOP(A, W, CDIM)

    float* stats = reinterpret_cast<float*>(smem);
    const int gid = lane >> 2, tig = lane & 3;
    const int shift = block_id[0] & 1;
    const int* ip = inds_all + ((size_t)shift * 2 + layer) * NVOX;
    int vrow[2][2];
#pragma unroll
    for (int mt = 0; mt < 2; mt++) {
#pragma unroll
        for (int mm = 0; mm < 2; mm++) {
            int rloc = wm + mt * 16 + mm * 8 + gid;
            int v = ip[m0 + rloc];
            vrow[mt][mm] = v;
            float s = 0.f, s2 = 0.f;
#pragma unroll
            for (int nt = 0; nt < 6; nt++) {
                int n = wn + nt * 8 + tig * 2;
                float2 c = *reinterpret_cast<const float2*>(cur + (size_t)v * CDIM + n);
                float a0 = acc[mt][nt][mm * 2]     + bias[n]     + c.x;
                float a1 = acc[mt][nt][mm * 2 + 1] + bias[n + 1] + c.y;
                acc[mt][nt][mm * 2] = a0; acc[mt][nt][mm * 2 + 1] = a1;
                s += a0 + a1; s2 += a0 * a0 + a1 * a1;
            }
            s  += __shfl_xor_sync(0xffffffffu, s, 1);  s  += __shfl_xor_sync(0xffffffffu, s, 2);
            s2 += __shfl_xor_sync(0xffffffffu, s2, 1); s2 += __shfl_xor_sync(0xffffffffu, s2, 2);
            if (tig == 0) {
                stats[((wid >> 1) * 64 + rloc) * 2]     = s;
                stats[((wid >> 1) * 64 + rloc) * 2 + 1] = s2;
            }
        }
    }
    __syncthreads();
#pragma unroll
    for (int mt = 0; mt < 2; mt++) {
#pragma unroll
        for (int mm = 0; mm < 2; mm++) {
            int rloc = wm + mt * 16 + mm * 8 + gid;
            int v = vrow[mt][mm];
            float S = 0.f, S2 = 0.f;
#pragma unroll
            for (int g = 0; g < 4; g++) {
                S  += stats[(g * 64 + rloc) * 2];
                S2 += stats[(g * 64 + rloc) * 2 + 1];
            }
            float mean = S * (1.0f / CDIM);
            float var = S2 * (1.0f / CDIM) - mean * mean;
            float rs = rsqrtf(var + 1e-5f);
#pragma unroll
            for (int nt = 0; nt < 6; nt++) {
                int n = wn + nt * 8 + tig * 2;
                float o0 = (acc[mt][nt][mm * 2]     - mean) * rs * lnw[n]     + lnb[n];
                float o1 = (acc[mt][nt][mm * 2 + 1] - mean) * rs * lnw[n + 1] + lnb[n + 1];
                *reinterpret_cast<float2*>(x32 + (size_t)v * CDIM + n) = make_float2(o0, o1);
                *reinterpret_cast<__nv_bfloat162*>(x16 + (size_t)v * CDIM + n) =
                    __floats2bfloat162_rn(o0, o1);
            }
        }
    }
}

// ---------------------------------------------------------------------------
// Fused lin2 + LN2 + LN3 (voxel-order rows).
// ---------------------------------------------------------------------------
__global__ __launch_bounds__(256) void gemm_ffn_ln23_kernel(
        const __nv_bfloat16* __restrict__ A,
        const __nv_bfloat16* __restrict__ W,
        const float* __restrict__ bias,
        const float* __restrict__ x32,
        const float* __restrict__ cur,
        const float* __restrict__ w2, const float* __restrict__ b2,
        const float* __restrict__ w3, const float* __restrict__ b3,
        float* __restrict__ outp) {
    extern __shared__ unsigned char smem[];
    const uint32_t sbase = (uint32_t)__cvta_generic_to_shared(smem);
    const int tid = threadIdx.x;
    const int lane = tid & 31;
    const int wid = tid >> 5;
    const int wm = (wid & 1) * 32;
    const int wn = (wid >> 1) * 48;
    const int m0 = blockIdx.x * 64;

    FUSED_MAINLOOP(A, W, DFF)

    float* stats = reinterpret_cast<float*>(smem);
    const int gid = lane >> 2, tig = lane & 3;

#pragma unroll
    for (int mt = 0; mt < 2; mt++) {
#pragma unroll
        for (int mm = 0; mm < 2; mm++) {
            int rloc = wm + mt * 16 + mm * 8 + gid;
            int v = m0 + rloc;
            float s = 0.f, s2 = 0.f;
#pragma unroll
            for (int nt = 0; nt < 6; nt++) {
                int n = wn + nt * 8 + tig * 2;
                float2 xr = *reinterpret_cast<const float2*>(x32 + (size_t)v * CDIM + n);
                float a0 = acc[mt][nt][mm * 2]     + bias[n]     + xr.x;
                float a1 = acc[mt][nt][mm * 2 + 1] + bias[n + 1] + xr.y;
                acc[mt][nt][mm * 2] = a0; acc[mt][nt][mm * 2 + 1] = a1;
                s += a0 + a1; s2 += a0 * a0 + a1 * a1;
            }
            s  += __shfl_xor_sync(0xffffffffu, s, 1);  s  += __shfl_xor_sync(0xffffffffu, s, 2);
            s2 += __shfl_xor_sync(0xffffffffu, s2, 1); s2 += __shfl_xor_sync(0xffffffffu, s2, 2);
            if (tig == 0) {
                stats[((wid >> 1) * 64 + rloc) * 2]     = s;
                stats[((wid >> 1) * 64 + rloc) * 2 + 1] = s2;
            }
        }
    }
    __syncthreads();

    float sB[2][2], s2B[2][2];
#pragma unroll
    for (int mt = 0; mt < 2; mt++) {
#pragma unroll
        for (int mm = 0; mm < 2; mm++) {
            int rloc = wm + mt * 16 + mm * 8 + gid;
            int v = m0 + rloc;
            float S = 0.f, S2 = 0.f;
#pragma unroll
            for (int g = 0; g < 4; g++) {
                S  += stats[(g * 64 + rloc) * 2];
                S2 += stats[(g * 64 + rloc) * 2 + 1];
            }
            float mean = S * (1.0f / CDIM);
            float var = S2 * (1.0f / CDIM) - mean * mean;
            float rs = rsqrtf(var + 1e-5f);
            float s = 0.f, s2 = 0.f;
#pragma unroll
            for (int nt = 0; nt < 6; nt++) {
                int n = wn + nt * 8 + tig * 2;
                float2 cv = *reinterpret_cast<const float2*>(cur + (size_t)v * CDIM + n);
                float t0 = (acc[mt][nt][mm * 2]     - mean) * rs * w2[n]     + b2[n]     + cv.x;
                float t1 = (acc[mt][nt][mm * 2 + 1] - mean) * rs * w2[n + 1] + b2[n + 1] + cv.y;
                acc[mt][nt][mm * 2] = t0; acc[mt][nt][mm * 2 + 1] = t1;
                s += t0 + t1; s2 += t0 * t0 + t1 * t1;
            }
            s  += __shfl_xor_sync(0xffffffffu, s, 1);  s  += __shfl_xor_sync(0xffffffffu, s, 2);
            s2 += __shfl_xor_sync(0xffffffffu, s2, 1); s2 += __shfl_xor_sync(0xffffffffu, s2, 2);
            sB[mt][mm] = s; s2B[mt][mm] = s2;
        }
    }
    __syncthreads();
#pragma unroll
    for (int mt = 0; mt < 2; mt++)
#pragma unroll
        for (int mm = 0; mm < 2; mm++) {
            int rloc = wm + mt * 16 + mm * 8 + gid;
            if (tig == 0) {
                stats[((wid >> 1) * 64 + rloc) * 2]     = sB[mt][mm];
                stats[((wid >> 1) * 64 + rloc) * 2 + 1] = s2B[mt][mm];
            }
        }
    __syncthreads();

#pragma unroll
    for (int mt = 0; mt < 2; mt++) {
#pragma unroll
        for (int mm = 0; mm < 2; mm++) {
            int rloc = wm + mt * 16 + mm * 8 + gid;
            int v = m0 + rloc;
            float S = 0.f, S2 = 0.f;
#pragma unroll
            for (int g = 0; g < 4; g++) {
                S  += stats[(g * 64 + rloc) * 2];
                S2 += stats[(g * 64 + rloc) * 2 + 1];
            }
            float mean = S * (1.0f / CDIM);
            float var = S2 * (1.0f / CDIM) - mean * mean;
            float rs = rsqrtf(var + 1e-5f);
#pragma unroll
            for (int nt = 0; nt < 6; nt++) {
                int n = wn + nt * 8 + tig * 2;
                float o0 = (acc[mt][nt][mm * 2]     - mean) * rs * w3[n]     + b3[n];
                float o1 = (acc[mt][nt][mm * 2 + 1] - mean) * rs * w3[n + 1] + b3[n + 1];
                *reinterpret_cast<float2*>(outp + (size_t)v * CDIM + n) = make_float2(o0, o1);
            }
        }
    }
}

// ---------------------------------------------------------------------------
// Single merged weight converter
// ---------------------------------------------------------------------------
__global__ void cvt_all_kernel(const float* __restrict__ ipw,
                               const float* __restrict__ opw,
                               const float* __restrict__ l1w,
                               const float* __restrict__ l2w,
                               __nv_bfloat16* __restrict__ dst) {
    int i = blockIdx.x * blockDim.x + threadIdx.x;
    const int N4 = W16_TOT / 4;
    if (i >= N4) return;
    int e = i * 4;
    const float* src;
    int off;
    if (e < OPW_OFF)      { src = ipw; off = e - IPW_OFF; }
    else if (e < L1W_OFF) { src = opw; off = e - OPW_OFF; }
    else if (e < L2W_OFF) { src = l1w; off = e - L1W_OFF; }
    else                  { src = l2w; off = e - L2W_OFF; }
    float4 v = *reinterpret_cast<const float4*>(src + off);
    reinterpret_cast<__nv_bfloat162*>(dst)[i * 2 + 0] = __floats2bfloat162_rn(v.x, v.y);
    reinterpret_cast<__nv_bfloat162*>(dst)[i * 2 + 1] = __floats2bfloat162_rn(v.z, v.w);
}

// ---------------------------------------------------------------------------
// Prep (coalesced, voxel order): qin16 = bf16(cur+pos); feat16 = bf16(cur)
// ---------------------------------------------------------------------------
__global__ void prep_kernel(const float* __restrict__ cur,
                            const float* __restrict__ pos,
                            __nv_bfloat16* __restrict__ qin,
                            __nv_bfloat16* __restrict__ feat) {
    int gid = blockIdx.x * blockDim.x + threadIdx.x;
    const int TOT = NVOX * (CDIM / 4);
    if (gid >= TOT) return;
    float4 f = reinterpret_cast<const float4*>(cur)[gid];
    float4 pp = reinterpret_cast<const float4*>(pos)[gid];
    __nv_bfloat162* f2 = reinterpret_cast<__nv_bfloat162*>(feat);
    __nv_bfloat162* q2 = reinterpret_cast<__nv_bfloat162*>(qin);
    f2[gid * 2 + 0] = __floats2bfloat162_rn(f.x, f.y);
    f2[gid * 2 + 1] = __floats2bfloat162_rn(f.z, f.w);
    q2[gid * 2 + 0] = __floats2bfloat162_rn(f.x + pp.x, f.y + pp.y);
    q2[gid * 2 + 1] = __floats2bfloat162_rn(f.z + pp.z, f.w + pp.w);
}

// ---------------------------------------------------------------------------
// Attention: one block per set, 288 threads = (36 rows x 8 heads).
// Inputs voxel-ordered (indirect gather via inds); output SET-ordered.
// All smem reads are 128-bit (3 uint4 per 24-element head row).
// ---------------------------------------------------------------------------
__global__ __launch_bounds__(288) void attn_kernel(const __nv_bfloat16* __restrict__ qk,
                                                   const __nv_bfloat16* __restrict__ v,
                                                   const int* __restrict__ inds_all,
                                                   const int* __restrict__ block_id,
                                                   int layer,
                                                   __nv_bfloat16* __restrict__ o) {
    __shared__ __nv_bfloat16 qks[SETSZ * 384];
    __shared__ __nv_bfloat16 vs[SETSZ * CDIM];
    __shared__ int vids[SETSZ];
    int s = blockIdx.x;
    int tid = threadIdx.x;

    if (tid < SETSZ) {
        int shift = block_id[0] & 1;
        vids[tid] = inds_all[((size_t)shift * 2 + layer) * NVOX + s * SETSZ + tid];
    }
    __syncthreads();

    const uint4* qk4 = reinterpret_cast<const uint4*>(qk);
    const uint4* v4 = reinterpret_cast<const uint4*>(v);
    for (int idx = tid; idx < SETSZ * 48; idx += 288) {
        int row = idx / 48, c = idx % 48;
        reinterpret_cast<uint4*>(qks)[row * 48 + c] = qk4[(size_t)vids[row] * 48 + c];
    }
    for (int idx = tid; idx < SETSZ * 24; idx += 288) {
        int row = idx / 24, c = idx % 24;
        reinterpret_cast<uint4*>(vs)[row * 24 + c] = v4[(size_t)vids[row] * 24 + c];
    }
    __syncthreads();

    int l = tid % SETSZ;
    int h = tid / SETSZ;

    // Load q row (24 bf16 = 3 uint4), unpack to fp32
    float qr[DH];
    {
        const uint4* qrow = reinterpret_cast<const uint4*>(qks + l * 384 + h * DH);
#pragma unroll
        for (int c = 0; c < 3; c++) {
            uint4 u = qrow[c];
            unpack8(u, qr + c * 8);
        }
    }

    const float scale = 0.20412414523193154f;
    float sc[SETSZ];
    float mx = -1e30f;
#pragma unroll 4
    for (int m = 0; m < SETSZ; m++) {
        const uint4* krow = reinterpret_cast<const uint4*>(qks + m * 384 + 192 + h * DH);
        float kf[DH];
#pragma unroll
        for (int c = 0; c < 3; c++) unpack8(krow[c], kf + c * 8);
        float dot = 0.f;
#pragma unroll
        for (int d = 0; d < DH; d++) dot += qr[d] * kf[d];
        dot *= scale;
        sc[m] = dot;
        mx = fmaxf(mx, dot);
    }
    float sum = 0.f;
#pragma unroll 4
    for (int m = 0; m < SETSZ; m++) {
        sc[m] = expf(sc[m] - mx);
        sum += sc[m];
    }
    float inv = 1.0f / sum;

    // attn @ V : accumulate full 24-wide output row in registers
    float acc[DH];
#pragma unroll
    for (int d = 0; d < DH; d++) acc[d] = 0.f;
#pragma unroll 4
    for (int m = 0; m < SETSZ; m++) {
        const uint4* vrow = reinterpret_cast<const uint4*>(vs + m * CDIM + h * DH);
        float vf[DH];
#pragma unroll
        for (int c = 0; c < 3; c++) unpack8(vrow[c], vf + c * 8);
        float p = sc[m];
#pragma unroll
        for (int d = 0; d < DH; d++) acc[d] += p * vf[d];
    }

    __nv_bfloat162* o2 = reinterpret_cast<__nv_bfloat162*>(
        o + (size_t)s * SETSZ * CDIM + l * CDIM + h * DH);
#pragma unroll
    for (int d2 = 0; d2 < DH / 2; d2++)
        o2[d2] = __floats2bfloat162_rn(acc[d2 * 2] * inv, acc[d2 * 2 + 1] * inv);
}

// ---------------------------------------------------------------------------
// Host orchestration
// ---------------------------------------------------------------------------
extern "C" void kernel_launch(void* const* d_in, const int* in_sizes, int n_in,
                              void* d_out, int out_size) {
    (void)in_sizes; (void)n_in; (void)out_size;
    const float* src  = (const float*)d_in[0];
    const int*   inds = (const int*)d_in[1];
    const float* pos  = (const float*)d_in[3];
    const int*   bid  = (const int*)d_in[4];
    const float* ipw  = (const float*)d_in[5];
    const float* ipb  = (const float*)d_in[6];
    const float* opw  = (const float*)d_in[7];
    const float* opb  = (const float*)d_in[8];
    const float* l1w  = (const float*)d_in[9];
    const float* l1b  = (const float*)d_in[10];
    const float* l2w  = (const float*)d_in[11];
    const float* l2b  = (const float*)d_in[12];
    const float* n1w  = (const float*)d_in[13];
    const float* n1b  = (const float*)d_in[14];
    const float* n2w  = (const float*)d_in[15];
    const float* n2b  = (const float*)d_in[16];
    const float* n3w  = (const float*)d_in[17];
    const float* n3b  = (const float*)d_in[18];

    float* out = (float*)d_out;

    __nv_bfloat16 *qk16, *qin16, *feat16, *v16, *x16, *h16, *w16;
    float *x32;
    cudaGetSymbolAddress((void**)&qk16, g_qk16);
    cudaGetSymbolAddress((void**)&qin16, g_qin16);
    cudaGetSymbolAddress((void**)&feat16, g_feat16);
    cudaGetSymbolAddress((void**)&v16, g_v16);
    cudaGetSymbolAddress((void**)&x16, g_x16);
    cudaGetSymbolAddress((void**)&h16, g_h16);
    cudaGetSymbolAddress((void**)&w16, g_w16);
    cudaGetSymbolAddress((void**)&x32, g_x32);

    cudaFuncSetAttribute((const void*)gemm_bf16_kernel<__nv_bfloat16, true>,
                         cudaFuncAttributeMaxDynamicSharedMemorySize, GEMM_SMEM);
    cudaFuncSetAttribute((const void*)qkv_gemm_kernel,
                         cudaFuncAttributeMaxDynamicSharedMemorySize, GEMM_SMEM);
    cudaFuncSetAttribute((const void*)gemm_op_ln1_kernel,
                         cudaFuncAttributeMaxDynamicSharedMemorySize, FUSED_SMEM);
    cudaFuncSetAttribute((const void*)gemm_ffn_ln23_kernel,
                         cudaFuncAttributeMaxDynamicSharedMemorySize, FUSED_SMEM);

    cvt_all_kernel<<<(W16_TOT / 4 + 255) / 256, 256>>>(ipw, opw, l1w, l2w, w16);

    const int TOT4 = NVOX * (CDIM / 4);
    dim3 pgrid((TOT4 + 255) / 256);
    dim3 gridQKV(9, NVOX / 256);
    dim3 grid768(DFF / 64, NVOX / 256);
    dim3 fgrid(NVOX / 64);

    for (int i = 0; i < 2; i++) {
        const __nv_bfloat16* Wqkv = w16 + IPW_OFF + (size_t)i * 3 * CDIM * CDIM;
        const float* bqkv = ipb + (size_t)i * 3 * CDIM;
        const float* posL = pos + (size_t)i * NVOX * CDIM;
        const float* cur = (i == 0) ? src : out;

        prep_kernel<<<pgrid, 256>>>(cur, posL, qin16, feat16);

        qkv_gemm_kernel<<<gridQKV, 256, GEMM_SMEM>>>(
            qin16, feat16, Wqkv, bqkv, qk16, v16);

        attn_kernel<<<NSET, 288>>>(qk16, v16, inds, bid, i, qin16);

        gemm_op_ln1_kernel<<<fgrid, 256, FUSED_SMEM>>>(
            qin16, w16 + OPW_OFF + (size_t)i * CDIM * CDIM, opb + (size_t)i * CDIM,
            cur, inds, bid, i, n1w + i * CDIM, n1b + i * CDIM, x32, x16);

        gemm_bf16_kernel<__nv_bfloat16, true><<<grid768, 256, GEMM_SMEM>>>(
            x16, w16 + L1W_OFF + (size_t)i * DFF * CDIM, l1b + (size_t)i * DFF,
            h16, CDIM, DFF);

        gemm_ffn_ln23_kernel<<<fgrid, 256, FUSED_SMEM>>>(
            h16, w16 + L2W_OFF + (size_t)i * CDIM * DFF, l2b + (size_t)i * CDIM,
            x32, cur, n2w + i * CDIM, n2b + i * CDIM,
            n3w + i * CDIM, n3b + i * CDIM, out);
    }
}